// round 4
// baseline (speedup 1.0000x reference)
#include <cuda_runtime.h>

#define NA 100000
#define NP 3200000
#define FA 75
#define FPR 14
#define HH 50
#define FO 50
#define XS 52   // padded row stride of X1/X2 (50 data + 2 zero), 16B-aligned rows

// ---------------- scratch (device globals; no allocs allowed) ----------------
__device__ float g_AA[NA * HH];   // relu(af @ W_AA^T + b_AA)
__device__ float g_X1[NA * XS];   // af @ W_AP[:, :75]^T   (no bias), cols 50,51 = 0
__device__ float g_X2[NA * XS];   // af @ W_AP[:, 75:]^T   (no bias), cols 50,51 = 0
__device__ float g_PA[NA * HH];   // segment-summed relu(pf @ W_PA^T + b_PA)

__device__ __forceinline__ float relu_(float x) { return fmaxf(x, 0.0f); }

// packed fp32x2 FMA (Blackwell): d = a*b + d, lane-wise on 64-bit pairs
__device__ __forceinline__ void fma2_(unsigned long long& d,
                                      unsigned long long a,
                                      unsigned long long b) {
    asm("fma.rn.f32x2 %0, %1, %2, %0;" : "+l"(d) : "l"(a), "l"(b));
}
__device__ __forceinline__ unsigned long long dup_(float x) {
    unsigned long long r;
    asm("mov.b64 %0, {%1, %1};" : "=l"(r) : "f"(x));
    return r;
}
__device__ __forceinline__ float2 unpk_(unsigned long long v) {
    float2 f;
    asm("mov.b64 {%0, %1}, %2;" : "=f"(f.x), "=f"(f.y) : "l"(v));
    return f;
}

// =====================================================================
// K1: atom-side precompute, merged.  grid = ceil(NA/64), 256 threads.
//   mat 0: g_AA = relu(af @ W_AA^T + b_AA)   (also zeroes g_PA, X pads)
//   mat 1: g_X1 = af @ W1^T     mat 2: g_X2 = af @ W2^T
// =====================================================================
__global__ __launch_bounds__(256) void atom_pre_kernel(
    const float* __restrict__ af,
    const float* __restrict__ W_AA, const float* __restrict__ b_AA,
    const float* __restrict__ W_AP)
{
    __shared__ __align__(16) float AsT[76 * 68];
    __shared__ __align__(16) float BsT[76 * 68];
    __shared__ float bsh[64];

    const int abase = blockIdx.x * 64;
    const int tid = threadIdx.x;

    for (int idx = tid; idx < 64 * 76; idx += 256) {
        int k = idx % 76, m = idx / 76;
        int a = abase + m;
        AsT[k * 68 + m] = (k < FA && a < NA) ? af[a * FA + k] : 0.0f;
    }
    for (int idx = tid; idx < 64 * HH; idx += 256) {
        int m = idx / HH, o = idx % HH;
        int a = abase + m;
        if (a < NA) g_PA[a * HH + o] = 0.0f;
    }
    // zero the X pad columns (50,51)
    for (int idx = tid; idx < 64 * 2; idx += 256) {
        int m = idx >> 1, o = 50 + (idx & 1);
        int a = abase + m;
        if (a < NA) { g_X1[(size_t)a * XS + o] = 0.0f; g_X2[(size_t)a * XS + o] = 0.0f; }
    }
    if (tid < 64) bsh[tid] = (tid < HH) ? b_AA[tid] : 0.0f;

    const int tm = tid >> 4, tn = tid & 15;
    const int m0 = tm * 4, n0 = tn * 4;

    for (int mat = 0; mat < 3; mat++) {
        __syncthreads();
        const float* W; int ws, wo;
        if (mat == 0) { W = W_AA; ws = FA;     wo = 0; }
        else          { W = W_AP; ws = 2 * FA; wo = (mat == 1) ? 0 : FA; }
        for (int idx = tid; idx < 64 * 76; idx += 256) {
            int k = idx % 76, o = idx / 76;
            BsT[k * 68 + o] = (k < FA && o < HH) ? W[o * ws + wo + k] : 0.0f;
        }
        __syncthreads();

        unsigned long long acc2[2][4];
#pragma unroll
        for (int rp = 0; rp < 2; rp++)
#pragma unroll
            for (int c = 0; c < 4; c++) acc2[rp][c] = 0ull;

#pragma unroll 5
        for (int k = 0; k < 75; k++) {
            ulonglong2 a2 = *(const ulonglong2*)&AsT[k * 68 + m0];
            float4 b4 = *(const float4*)&BsT[k * 68 + n0];
            unsigned long long av[2] = {a2.x, a2.y};
            unsigned long long bd[4] = {dup_(b4.x), dup_(b4.y), dup_(b4.z), dup_(b4.w)};
#pragma unroll
            for (int rp = 0; rp < 2; rp++)
#pragma unroll
                for (int c = 0; c < 4; c++) fma2_(acc2[rp][c], av[rp], bd[c]);
        }

        float* dst = (mat == 0) ? g_AA : ((mat == 1) ? g_X1 : g_X2);
        const int ds = (mat == 0) ? HH : XS;
#pragma unroll
        for (int rp = 0; rp < 2; rp++) {
#pragma unroll
            for (int c = 0; c < 4; c++) {
                int o = n0 + c;
                if (o < HH) {
                    float2 f2 = unpk_(acc2[rp][c]);
                    int a0 = abase + m0 + 2 * rp;
                    if (mat == 0) {
                        f2.x = relu_(f2.x + bsh[o]);
                        f2.y = relu_(f2.y + bsh[o]);
                    }
                    if (a0 < NA)     dst[(size_t)a0 * ds + o]       = f2.x;
                    if (a0 + 1 < NA) dst[(size_t)(a0 + 1) * ds + o] = f2.y;
                }
            }
        }
    }
}

// =====================================================================
// K2 (megakernel), 128-pair tiles, 256 threads, 2 blocks/SM.
// Phases: stage -> P1(PA)+PP -> sync -> P2(segsum) -> sync -> P3(S) -> sync -> P4
// =====================================================================
#define CTS 132
#define WTS 68
// CT 100*CTS, WT 100*WTS, pfT 16*CTS, WpaT/WppT 16*WTS, 4 bias(52), idx/psv/heads/nh
#define PAIR_SMEM_FLOATS (100*CTS + 100*WTS + 16*CTS + 2*16*WTS + 4*52 + 256 + 132 + 128 + 4)
#define PAIR_SMEM_BYTES  (PAIR_SMEM_FLOATS * 4)

// one S-chunk: rows k0..k0+3 (FULL) or k0..k0+1 (tail, k0=48)
template <bool FULL>
__device__ __forceinline__ void s_chunk(
    int k0, int p, float* CT, const float* sbAP,
    const float* X1i, const float* X2i, const float* X1j, const float* X2j)
{
    float4 a = *(const float4*)(X1i + k0);
    float4 b = *(const float4*)(X2j + k0);
    float4 d = *(const float4*)(X1j + k0);
    float4 e = *(const float4*)(X2i + k0);
    float4 bi = *(const float4*)(sbAP + k0);
    float s0 = relu_(a.x + b.x + bi.x) + relu_(d.x + e.x + bi.x);
    float s1 = relu_(a.y + b.y + bi.y) + relu_(d.y + e.y + bi.y);
    CT[(k0 + 0) * CTS + p] = s0;
    CT[(k0 + 1) * CTS + p] = s1;
    if (FULL) {
        float s2 = relu_(a.z + b.z + bi.z) + relu_(d.z + e.z + bi.z);
        float s3 = relu_(a.w + b.w + bi.w) + relu_(d.w + e.w + bi.w);
        CT[(k0 + 2) * CTS + p] = s2;
        CT[(k0 + 3) * CTS + p] = s3;
    }
}

__global__ __launch_bounds__(256, 2) void pair_kernel(
    const float* __restrict__ pf,
    const int*   __restrict__ split,
    const int*   __restrict__ atp,
    const float* __restrict__ W_PA, const float* __restrict__ b_PA,
    const float* __restrict__ W_PP, const float* __restrict__ b_PP,
    const float* __restrict__ W_P,  const float* __restrict__ b_P,
    const float* __restrict__ b_AP,
    float* __restrict__ outP)
{
    extern __shared__ __align__(16) float sm[];
    float* CT   = sm;                       // [100][CTS]
    float* WT   = CT + 100 * CTS;           // [100][WTS]
    float* pfT  = WT + 100 * WTS;           // [16][CTS]
    float* WpaT = pfT + 16 * CTS;           // [16][WTS]
    float* WppT = WpaT + 16 * WTS;          // [16][WTS]
    float* sbAP = WppT + 16 * WTS;          // 52 (pad zeros)
    float* sbPP = sbAP + 52;
    float* sbPA = sbPP + 52;
    float* sbP  = sbPA + 52;
    int* sidx   = (int*)(sbP + 52);         // 256
    int* spsv   = sidx + 256;               // 132
    int* sheads = spsv + 132;               // 128
    int* snh    = sheads + 128;             // 1

    const int p0  = blockIdx.x * 128;
    const int tid = threadIdx.x;

    // ---------------- P0: staging ----------------
    for (int idx = tid; idx < 128 * 16; idx += 256) {
        int kk = idx & 15, p = idx >> 4;
        pfT[kk * CTS + p] = (kk < FPR) ? __ldcs(&pf[(p0 + p) * FPR + kk]) : 0.0f;
    }
    for (int idx = tid; idx < 64 * 100; idx += 256) {
        int k = idx % 100, o = idx / 100;
        WT[k * WTS + o] = (o < FO) ? W_P[o * 2 * HH + k] : 0.0f;
    }
    for (int idx = tid; idx < 64 * 16; idx += 256) {
        int k = idx & 15, o = idx >> 4;
        bool v = (k < FPR && o < HH);
        WpaT[k * WTS + o] = v ? W_PA[o * FPR + k] : 0.0f;
        WppT[k * WTS + o] = v ? W_PP[o * FPR + k] : 0.0f;
    }
    if (tid < 52) {
        sbAP[tid] = (tid < HH) ? b_AP[tid] : 0.0f;
        sbPP[tid] = (tid < HH) ? b_PP[tid] : 0.0f;
        sbPA[tid] = (tid < HH) ? b_PA[tid] : 0.0f;
        sbP[tid]  = (tid < FO) ? b_P[tid]  : 0.0f;
    }
    sidx[tid] = atp[p0 * 2 + tid];
    if (tid < 129) {
        // spsv[0] = -1 ALWAYS: force a run head at t=0 so boundary-crossing
        // runs are accumulated from both tiles (atomics commute).
        spsv[tid] = (tid == 0) ? -1 : split[p0 + tid - 1];
    }
    if (tid == 0) *snh = 0;
    __syncthreads();

    const int tm = tid >> 4, tn = tid & 15;
    const int m0 = tm * 8, n0 = tn * 4;

    // ---------------- P1: PA -> CT rows [0,50);  PP -> CT rows [50,100) ----------------
#pragma unroll
    for (int g = 0; g < 2; g++) {
        const float* Wg = g ? WppT : WpaT;
        const float* bg = g ? sbPP : sbPA;
        const int ro = g ? HH : 0;
        unsigned long long acc2[4][4];
#pragma unroll
        for (int rp = 0; rp < 4; rp++)
#pragma unroll
            for (int c = 0; c < 4; c++) acc2[rp][c] = 0ull;
#pragma unroll
        for (int k = 0; k < FPR; k++) {
            float4 b4 = *(const float4*)&Wg[k * WTS + n0];
            ulonglong2 a01 = *(const ulonglong2*)&pfT[k * CTS + m0];
            ulonglong2 a23 = *(const ulonglong2*)&pfT[k * CTS + m0 + 4];
            unsigned long long av[4] = {a01.x, a01.y, a23.x, a23.y};
            unsigned long long bd[4] = {dup_(b4.x), dup_(b4.y), dup_(b4.z), dup_(b4.w)};
#pragma unroll
            for (int rp = 0; rp < 4; rp++)
#pragma unroll
                for (int c = 0; c < 4; c++) fma2_(acc2[rp][c], av[rp], bd[c]);
        }
#pragma unroll
        for (int c = 0; c < 4; c++) {
            int o = n0 + c;
            if (o < HH) {
                float b = bg[o];
#pragma unroll
                for (int rp = 0; rp < 4; rp++) {
                    float2 f2 = unpk_(acc2[rp][c]);
                    CT[(ro + o) * CTS + m0 + 2 * rp]     = relu_(f2.x + b);
                    CT[(ro + o) * CTS + m0 + 2 * rp + 1] = relu_(f2.y + b);
                }
            }
        }
    }
    __syncthreads();

    // ---------------- P2: sorted-run reduce + atomics into g_PA ----------------
    if (tid < 128) {
        if (spsv[tid + 1] != spsv[tid]) {
            int pos = atomicAdd(snh, 1);
            sheads[pos] = tid;
        }
    }
    __syncthreads();
    {
        int nh = *snh;
        for (int t = tid; t < nh * 64; t += 256) {
            int o = t & 63, hi = t >> 6;
            if (o < HH) {
                int h = sheads[hi];
                int seg = spsv[h + 1];
                float s = 0.0f;
                int q = h;
                while (q < 128 && spsv[q + 1] == seg) { s += CT[o * CTS + q]; q++; }
                atomicAdd(&g_PA[seg * HH + o], s);
            }
        }
    }
    __syncthreads();

    // ---------------- P3: S -> CT rows [0,50)  (float4 gathers, 2 thr/pair) ----------------
    {
        const int p  = tid & 127;
        const int hf = tid >> 7;
        const int i = sidx[2 * p], j = sidx[2 * p + 1];
        const float* X1i = g_X1 + (size_t)i * XS;
        const float* X2i = g_X2 + (size_t)i * XS;
        const float* X1j = g_X1 + (size_t)j * XS;
        const float* X2j = g_X2 + (size_t)j * XS;
        if (hf == 0) {
#pragma unroll
            for (int c = 0; c < 7; c++)
                s_chunk<true>(c * 4, p, CT, sbAP, X1i, X2i, X1j, X2j);
        } else {
#pragma unroll
            for (int c = 7; c < 12; c++)
                s_chunk<true>(c * 4, p, CT, sbAP, X1i, X2i, X1j, X2j);
            s_chunk<false>(48, p, CT, sbAP, X1i, X2i, X1j, X2j);  // rows 48,49 only
        }
    }
    __syncthreads();

    // ---------------- P4: P = relu([S|PP] @ W_P^T + b_P), K = 100 ----------------
    {
        unsigned long long acc2[4][4];
#pragma unroll
        for (int rp = 0; rp < 4; rp++)
#pragma unroll
            for (int c = 0; c < 4; c++) acc2[rp][c] = 0ull;
#pragma unroll 4
        for (int k = 0; k < 100; k++) {
            float4 b4 = *(const float4*)&WT[k * WTS + n0];
            ulonglong2 a01 = *(const ulonglong2*)&CT[k * CTS + m0];
            ulonglong2 a23 = *(const ulonglong2*)&CT[k * CTS + m0 + 4];
            unsigned long long av[4] = {a01.x, a01.y, a23.x, a23.y};
            unsigned long long bd[4] = {dup_(b4.x), dup_(b4.y), dup_(b4.z), dup_(b4.w)};
#pragma unroll
            for (int rp = 0; rp < 4; rp++)
#pragma unroll
                for (int c = 0; c < 4; c++) fma2_(acc2[rp][c], av[rp], bd[c]);
        }
        if (n0 < FO) {
            float accf[8][4];
#pragma unroll
            for (int rp = 0; rp < 4; rp++)
#pragma unroll
                for (int c = 0; c < 4; c++) {
                    float2 f2 = unpk_(acc2[rp][c]);
                    accf[2 * rp][c]     = f2.x;
                    accf[2 * rp + 1][c] = f2.y;
                }
            float bb[4];
#pragma unroll
            for (int c = 0; c < 4; c++) bb[c] = sbP[n0 + c];
#pragma unroll
            for (int r = 0; r < 8; r++) {
                size_t p = (size_t)(p0 + m0 + r);
                float v0 = relu_(accf[r][0] + bb[0]);
                float v1 = relu_(accf[r][1] + bb[1]);
                float* dst = &outP[p * FO + n0];
                __stcs((float2*)dst, make_float2(v0, v1));
                if (n0 + 3 < FO) {
                    float v2 = relu_(accf[r][2] + bb[2]);
                    float v3 = relu_(accf[r][3] + bb[3]);
                    __stcs((float2*)(dst + 2), make_float2(v2, v3));
                }
            }
        }
    }
}

// =====================================================================
// K3: A = relu(concat([AA, PAseg]) @ W_A^T + b_A), K = 100
// =====================================================================
#define K3_SMEM_FLOATS (100*68 * 2 + 64)
#define K3_SMEM_BYTES  (K3_SMEM_FLOATS * 4)

__global__ __launch_bounds__(256) void atom_out_kernel(
    const float* __restrict__ W_A, const float* __restrict__ b_A,
    float* __restrict__ outA)
{
    extern __shared__ __align__(16) float sm3[];
    float* CcT = sm3;             // [100][68]
    float* BsT = CcT + 100 * 68;  // [100][68]
    float* bsh = BsT + 100 * 68;  // 64

    const int abase = blockIdx.x * 64;
    const int tid = threadIdx.x;

    for (int idx = tid; idx < 64 * 100; idx += 256) {
        int k = idx % 100, m = idx / 100;
        int a = abase + m;
        float v = 0.0f;
        if (a < NA) v = (k < HH) ? g_AA[a * HH + k] : g_PA[a * HH + (k - HH)];
        CcT[k * 68 + m] = v;
    }
    for (int idx = tid; idx < 64 * 100; idx += 256) {
        int k = idx % 100, o = idx / 100;
        BsT[k * 68 + o] = (o < FO) ? W_A[o * 2 * HH + k] : 0.0f;
    }
    if (tid < 64) bsh[tid] = (tid < FO) ? b_A[tid] : 0.0f;
    __syncthreads();

    const int tm = tid >> 4, tn = tid & 15;
    const int m0 = tm * 4, n0 = tn * 4;
    unsigned long long acc2[2][4];
#pragma unroll
    for (int rp = 0; rp < 2; rp++)
#pragma unroll
        for (int c = 0; c < 4; c++) acc2[rp][c] = 0ull;

#pragma unroll 4
    for (int k = 0; k < 100; k++) {
        ulonglong2 a2 = *(const ulonglong2*)&CcT[k * 68 + m0];
        float4 b4 = *(const float4*)&BsT[k * 68 + n0];
        unsigned long long av[2] = {a2.x, a2.y};
        unsigned long long bd[4] = {dup_(b4.x), dup_(b4.y), dup_(b4.z), dup_(b4.w)};
#pragma unroll
        for (int rp = 0; rp < 2; rp++)
#pragma unroll
            for (int c = 0; c < 4; c++) fma2_(acc2[rp][c], av[rp], bd[c]);
    }
#pragma unroll
    for (int rp = 0; rp < 2; rp++) {
#pragma unroll
        for (int c = 0; c < 4; c++) {
            int o = n0 + c;
            if (o < FO) {
                float2 f2 = unpk_(acc2[rp][c]);
                int a0 = abase + m0 + 2 * rp;
                if (a0 < NA)     outA[(size_t)a0 * FO + o]       = relu_(f2.x + bsh[o]);
                if (a0 + 1 < NA) outA[(size_t)(a0 + 1) * FO + o] = relu_(f2.y + bsh[o]);
            }
        }
    }
}

// =====================================================================
// launch
// =====================================================================
extern "C" void kernel_launch(void* const* d_in, const int* in_sizes, int n_in,
                              void* d_out, int out_size)
{
    const float* af    = (const float*)d_in[0];
    const float* pf    = (const float*)d_in[1];
    const int*   split = (const int*)  d_in[2];
    const int*   atp   = (const int*)  d_in[3];
    const float* W_AA  = (const float*)d_in[4];
    const float* b_AA  = (const float*)d_in[5];
    const float* W_PA  = (const float*)d_in[6];
    const float* b_PA  = (const float*)d_in[7];
    const float* W_A   = (const float*)d_in[8];
    const float* b_A   = (const float*)d_in[9];
    const float* W_AP  = (const float*)d_in[10];
    const float* b_AP  = (const float*)d_in[11];
    const float* W_PP  = (const float*)d_in[12];
    const float* b_PP  = (const float*)d_in[13];
    const float* W_P   = (const float*)d_in[14];
    const float* b_P   = (const float*)d_in[15];
    float* out = (float*)d_out;

    cudaFuncSetAttribute(pair_kernel, cudaFuncAttributeMaxDynamicSharedMemorySize, PAIR_SMEM_BYTES);
    cudaFuncSetAttribute(atom_out_kernel, cudaFuncAttributeMaxDynamicSharedMemorySize, K3_SMEM_BYTES);

    atom_pre_kernel<<<(NA + 63) / 64, 256>>>(af, W_AA, b_AA, W_AP);

    pair_kernel<<<NP / 128, 256, PAIR_SMEM_BYTES>>>(
        pf, split, atp, W_PA, b_PA, W_PP, b_PP, W_P, b_P, b_AP,
        out + (size_t)NA * FO);

    atom_out_kernel<<<(NA + 63) / 64, 256, K3_SMEM_BYTES>>>(W_A, b_A, out);
}

// round 5
// speedup vs baseline: 1.4208x; 1.4208x over previous
#include <cuda_runtime.h>

#define NA 100000
#define NP 3200000
#define FA 75
#define FPR 14
#define HH 50
#define FO 50
#define XS 52   // padded row stride of X1/X2 (50 data + 2 zero), 16B-aligned rows

// ---------------- scratch (device globals; no allocs allowed) ----------------
__device__ float g_AA[NA * HH];   // relu(af @ W_AA^T + b_AA)
__device__ float g_X1[NA * XS];   // af @ W_AP[:, :75]^T   (no bias), cols 50,51 = 0
__device__ float g_X2[NA * XS];   // af @ W_AP[:, 75:]^T   (no bias), cols 50,51 = 0
__device__ float g_PA[NA * HH];   // segment-summed relu(pf @ W_PA^T + b_PA)

__device__ __forceinline__ float relu_(float x) { return fmaxf(x, 0.0f); }

// packed fp32x2 FMA (Blackwell): d = a*b + d, lane-wise on 64-bit pairs
__device__ __forceinline__ void fma2_(unsigned long long& d,
                                      unsigned long long a,
                                      unsigned long long b) {
    asm("fma.rn.f32x2 %0, %1, %2, %0;" : "+l"(d) : "l"(a), "l"(b));
}
__device__ __forceinline__ unsigned long long dup_(float x) {
    unsigned long long r;
    asm("mov.b64 %0, {%1, %1};" : "=l"(r) : "f"(x));
    return r;
}
__device__ __forceinline__ float2 unpk_(unsigned long long v) {
    float2 f;
    asm("mov.b64 {%0, %1}, %2;" : "=f"(f.x), "=f"(f.y) : "l"(v));
    return f;
}

// =====================================================================
// K1: atom-side precompute, merged.  grid = ceil(NA/64), 256 threads.
//   mat 0: g_AA = relu(af @ W_AA^T + b_AA)   (also zeroes g_PA, X pads)
//   mat 1: g_X1 = af @ W1^T     mat 2: g_X2 = af @ W2^T
// =====================================================================
__global__ __launch_bounds__(256) void atom_pre_kernel(
    const float* __restrict__ af,
    const float* __restrict__ W_AA, const float* __restrict__ b_AA,
    const float* __restrict__ W_AP)
{
    __shared__ __align__(16) float AsT[76 * 68];
    __shared__ __align__(16) float BsT[76 * 68];
    __shared__ float bsh[64];

    const int abase = blockIdx.x * 64;
    const int tid = threadIdx.x;

    for (int idx = tid; idx < 64 * 76; idx += 256) {
        int k = idx % 76, m = idx / 76;
        int a = abase + m;
        AsT[k * 68 + m] = (k < FA && a < NA) ? af[a * FA + k] : 0.0f;
    }
    for (int idx = tid; idx < 64 * HH; idx += 256) {
        int m = idx / HH, o = idx % HH;
        int a = abase + m;
        if (a < NA) g_PA[a * HH + o] = 0.0f;
    }
    // zero the X pad columns (50,51)
    for (int idx = tid; idx < 64 * 2; idx += 256) {
        int m = idx >> 1, o = 50 + (idx & 1);
        int a = abase + m;
        if (a < NA) { g_X1[(size_t)a * XS + o] = 0.0f; g_X2[(size_t)a * XS + o] = 0.0f; }
    }
    if (tid < 64) bsh[tid] = (tid < HH) ? b_AA[tid] : 0.0f;

    const int tm = tid >> 4, tn = tid & 15;
    const int m0 = tm * 4, n0 = tn * 4;

    for (int mat = 0; mat < 3; mat++) {
        __syncthreads();
        const float* W; int ws, wo;
        if (mat == 0) { W = W_AA; ws = FA;     wo = 0; }
        else          { W = W_AP; ws = 2 * FA; wo = (mat == 1) ? 0 : FA; }
        for (int idx = tid; idx < 64 * 76; idx += 256) {
            int k = idx % 76, o = idx / 76;
            BsT[k * 68 + o] = (k < FA && o < HH) ? W[o * ws + wo + k] : 0.0f;
        }
        __syncthreads();

        unsigned long long acc2[2][4];
#pragma unroll
        for (int rp = 0; rp < 2; rp++)
#pragma unroll
            for (int c = 0; c < 4; c++) acc2[rp][c] = 0ull;

#pragma unroll 5
        for (int k = 0; k < 75; k++) {
            ulonglong2 a2 = *(const ulonglong2*)&AsT[k * 68 + m0];
            float4 b4 = *(const float4*)&BsT[k * 68 + n0];
            unsigned long long av[2] = {a2.x, a2.y};
            unsigned long long bd[4] = {dup_(b4.x), dup_(b4.y), dup_(b4.z), dup_(b4.w)};
#pragma unroll
            for (int rp = 0; rp < 2; rp++)
#pragma unroll
                for (int c = 0; c < 4; c++) fma2_(acc2[rp][c], av[rp], bd[c]);
        }

        float* dst = (mat == 0) ? g_AA : ((mat == 1) ? g_X1 : g_X2);
        const int ds = (mat == 0) ? HH : XS;
#pragma unroll
        for (int rp = 0; rp < 2; rp++) {
#pragma unroll
            for (int c = 0; c < 4; c++) {
                int o = n0 + c;
                if (o < HH) {
                    float2 f2 = unpk_(acc2[rp][c]);
                    int a0 = abase + m0 + 2 * rp;
                    if (mat == 0) {
                        f2.x = relu_(f2.x + bsh[o]);
                        f2.y = relu_(f2.y + bsh[o]);
                    }
                    if (a0 < NA)     dst[(size_t)a0 * ds + o]       = f2.x;
                    if (a0 + 1 < NA) dst[(size_t)(a0 + 1) * ds + o] = f2.y;
                }
            }
        }
    }
}

// =====================================================================
// K2 (megakernel), 128-pair tiles, 256 threads, 2 blocks/SM.
// Phases: stage -> P1(PA+PP) -> sync -> P2(segsum) -> sync -> P3(S) -> sync -> P4
// =====================================================================
#define CTS 132
#define WTS 68
#define PAIR_SMEM_FLOATS (100*CTS + 100*WTS + 16*CTS + 2*16*WTS + 4*52 + 256 + 132 + 128 + 4)
#define PAIR_SMEM_BYTES  (PAIR_SMEM_FLOATS * 4)

__global__ __launch_bounds__(256, 2) void pair_kernel(
    const float* __restrict__ pf,
    const int*   __restrict__ split,
    const int*   __restrict__ atp,
    const float* __restrict__ W_PA, const float* __restrict__ b_PA,
    const float* __restrict__ W_PP, const float* __restrict__ b_PP,
    const float* __restrict__ W_P,  const float* __restrict__ b_P,
    const float* __restrict__ b_AP,
    float* __restrict__ outP)
{
    extern __shared__ __align__(16) float sm[];
    float* CT   = sm;                       // [100][CTS]
    float* WT   = CT + 100 * CTS;           // [100][WTS]
    float* pfT  = WT + 100 * WTS;           // [16][CTS]
    float* WpaT = pfT + 16 * CTS;           // [16][WTS]
    float* WppT = WpaT + 16 * WTS;          // [16][WTS]
    float* sbAP = WppT + 16 * WTS;          // 52 (pad zeros)
    float* sbPP = sbAP + 52;
    float* sbPA = sbPP + 52;
    float* sbP  = sbPA + 52;
    int* sidx   = (int*)(sbP + 52);         // 256
    int* spsv   = sidx + 256;               // 132
    int* sheads = spsv + 132;               // 128
    int* snh    = sheads + 128;             // 1

    const int p0  = blockIdx.x * 128;
    const int tid = threadIdx.x;

    // ---------------- P0: staging ----------------
    for (int idx = tid; idx < 128 * 16; idx += 256) {
        int kk = idx & 15, p = idx >> 4;
        pfT[kk * CTS + p] = (kk < FPR) ? __ldcs(&pf[(p0 + p) * FPR + kk]) : 0.0f;
    }
    for (int idx = tid; idx < 64 * 100; idx += 256) {
        int k = idx % 100, o = idx / 100;
        WT[k * WTS + o] = (o < FO) ? W_P[o * 2 * HH + k] : 0.0f;
    }
    for (int idx = tid; idx < 64 * 16; idx += 256) {
        int k = idx & 15, o = idx >> 4;
        bool v = (k < FPR && o < HH);
        WpaT[k * WTS + o] = v ? W_PA[o * FPR + k] : 0.0f;
        WppT[k * WTS + o] = v ? W_PP[o * FPR + k] : 0.0f;
    }
    if (tid < 52) {
        sbAP[tid] = (tid < HH) ? b_AP[tid] : 0.0f;
        sbPP[tid] = (tid < HH) ? b_PP[tid] : 0.0f;
        sbPA[tid] = (tid < HH) ? b_PA[tid] : 0.0f;
        sbP[tid]  = (tid < FO) ? b_P[tid]  : 0.0f;
    }
    sidx[tid] = atp[p0 * 2 + tid];
    if (tid < 129) {
        // spsv[0] = -1 ALWAYS: force a run head at t=0 so boundary-crossing
        // runs are accumulated from both tiles (atomics commute).
        spsv[tid] = (tid == 0) ? -1 : split[p0 + tid - 1];
    }
    if (tid == 0) *snh = 0;
    __syncthreads();

    const int tm = tid >> 4, tn = tid & 15;
    const int m0 = tm * 8, n0 = tn * 4;

    // ---------------- P1: PA -> CT rows [0,50);  PP -> CT rows [50,100) ----------------
#pragma unroll
    for (int g = 0; g < 2; g++) {
        const float* Wg = g ? WppT : WpaT;
        const float* bg = g ? sbPP : sbPA;
        const int ro = g ? HH : 0;
        unsigned long long acc2[4][4];
#pragma unroll
        for (int rp = 0; rp < 4; rp++)
#pragma unroll
            for (int c = 0; c < 4; c++) acc2[rp][c] = 0ull;
#pragma unroll
        for (int k = 0; k < FPR; k++) {
            float4 b4 = *(const float4*)&Wg[k * WTS + n0];
            ulonglong2 a01 = *(const ulonglong2*)&pfT[k * CTS + m0];
            ulonglong2 a23 = *(const ulonglong2*)&pfT[k * CTS + m0 + 4];
            unsigned long long av[4] = {a01.x, a01.y, a23.x, a23.y};
            unsigned long long bd[4] = {dup_(b4.x), dup_(b4.y), dup_(b4.z), dup_(b4.w)};
#pragma unroll
            for (int rp = 0; rp < 4; rp++)
#pragma unroll
                for (int c = 0; c < 4; c++) fma2_(acc2[rp][c], av[rp], bd[c]);
        }
#pragma unroll
        for (int c = 0; c < 4; c++) {
            int o = n0 + c;
            if (o < HH) {
                float b = bg[o];
#pragma unroll
                for (int rp = 0; rp < 4; rp++) {
                    float2 f2 = unpk_(acc2[rp][c]);
                    CT[(ro + o) * CTS + m0 + 2 * rp]     = relu_(f2.x + b);
                    CT[(ro + o) * CTS + m0 + 2 * rp + 1] = relu_(f2.y + b);
                }
            }
        }
    }
    __syncthreads();

    // ---------------- P2: sorted-run reduce + atomics into g_PA ----------------
    if (tid < 128) {
        if (spsv[tid + 1] != spsv[tid]) {
            int pos = atomicAdd(snh, 1);
            sheads[pos] = tid;
        }
    }
    __syncthreads();
    {
        int nh = *snh;
        for (int t = tid; t < nh * 64; t += 256) {
            int o = t & 63, hi = t >> 6;
            if (o < HH) {
                int h = sheads[hi];
                int seg = spsv[h + 1];
                float s = 0.0f;
                int q = h;
                while (q < 128 && spsv[q + 1] == seg) { s += CT[o * CTS + q]; q++; }
                atomicAdd(&g_PA[seg * HH + o], s);
            }
        }
    }
    __syncthreads();

    // ---------------- P3: S -> CT rows [0,50) ----------------
    // Work item = (pair p, chunk c of 4 k-values). k-inner distribution:
    // consecutive threads walk k within the SAME atom rows -> a warp touches
    // ~2.5 rows -> few L1tex wavefronts per LDG (the R4 per-thread-per-pair
    // layout touched 32 rows per LDG and regressed 1.2ms).
    for (int idx = tid; idx < 128 * 13; idx += 256) {
        int p = idx / 13, c = idx % 13;
        int k0 = c * 4;
        int i = sidx[2 * p], j = sidx[2 * p + 1];
        float4 a = *(const float4*)(g_X1 + (size_t)i * XS + k0);
        float4 b = *(const float4*)(g_X2 + (size_t)j * XS + k0);
        float4 d = *(const float4*)(g_X1 + (size_t)j * XS + k0);
        float4 e = *(const float4*)(g_X2 + (size_t)i * XS + k0);
        float4 bi = *(const float4*)(sbAP + k0);
        float s0 = relu_(a.x + b.x + bi.x) + relu_(d.x + e.x + bi.x);
        float s1 = relu_(a.y + b.y + bi.y) + relu_(d.y + e.y + bi.y);
        CT[(k0 + 0) * CTS + p] = s0;
        CT[(k0 + 1) * CTS + p] = s1;
        if (c < 12) {   // rows 50,51 belong to PP — chunk 12 writes only k=48,49
            float s2 = relu_(a.z + b.z + bi.z) + relu_(d.z + e.z + bi.z);
            float s3 = relu_(a.w + b.w + bi.w) + relu_(d.w + e.w + bi.w);
            CT[(k0 + 2) * CTS + p] = s2;
            CT[(k0 + 3) * CTS + p] = s3;
        }
    }
    __syncthreads();

    // ---------------- P4: P = relu([S|PP] @ W_P^T + b_P), K = 100 ----------------
    {
        unsigned long long acc2[4][4];
#pragma unroll
        for (int rp = 0; rp < 4; rp++)
#pragma unroll
            for (int c = 0; c < 4; c++) acc2[rp][c] = 0ull;
#pragma unroll 4
        for (int k = 0; k < 100; k++) {
            float4 b4 = *(const float4*)&WT[k * WTS + n0];
            ulonglong2 a01 = *(const ulonglong2*)&CT[k * CTS + m0];
            ulonglong2 a23 = *(const ulonglong2*)&CT[k * CTS + m0 + 4];
            unsigned long long av[4] = {a01.x, a01.y, a23.x, a23.y};
            unsigned long long bd[4] = {dup_(b4.x), dup_(b4.y), dup_(b4.z), dup_(b4.w)};
#pragma unroll
            for (int rp = 0; rp < 4; rp++)
#pragma unroll
                for (int c = 0; c < 4; c++) fma2_(acc2[rp][c], av[rp], bd[c]);
        }
        if (n0 < FO) {
            float accf[8][4];
#pragma unroll
            for (int rp = 0; rp < 4; rp++)
#pragma unroll
                for (int c = 0; c < 4; c++) {
                    float2 f2 = unpk_(acc2[rp][c]);
                    accf[2 * rp][c]     = f2.x;
                    accf[2 * rp + 1][c] = f2.y;
                }
            float bb[4];
#pragma unroll
            for (int c = 0; c < 4; c++) bb[c] = sbP[n0 + c];
#pragma unroll
            for (int r = 0; r < 8; r++) {
                size_t p = (size_t)(p0 + m0 + r);
                float v0 = relu_(accf[r][0] + bb[0]);
                float v1 = relu_(accf[r][1] + bb[1]);
                float* dst = &outP[p * FO + n0];
                __stcs((float2*)dst, make_float2(v0, v1));
                if (n0 + 3 < FO) {
                    float v2 = relu_(accf[r][2] + bb[2]);
                    float v3 = relu_(accf[r][3] + bb[3]);
                    __stcs((float2*)(dst + 2), make_float2(v2, v3));
                }
            }
        }
    }
}

// =====================================================================
// K3: A = relu(concat([AA, PAseg]) @ W_A^T + b_A), K = 100
// =====================================================================
#define K3_SMEM_FLOATS (100*68 * 2 + 64)
#define K3_SMEM_BYTES  (K3_SMEM_FLOATS * 4)

__global__ __launch_bounds__(256) void atom_out_kernel(
    const float* __restrict__ W_A, const float* __restrict__ b_A,
    float* __restrict__ outA)
{
    extern __shared__ __align__(16) float sm3[];
    float* CcT = sm3;             // [100][68]
    float* BsT = CcT + 100 * 68;  // [100][68]
    float* bsh = BsT + 100 * 68;  // 64

    const int abase = blockIdx.x * 64;
    const int tid = threadIdx.x;

    for (int idx = tid; idx < 64 * 100; idx += 256) {
        int k = idx % 100, m = idx / 100;
        int a = abase + m;
        float v = 0.0f;
        if (a < NA) v = (k < HH) ? g_AA[a * HH + k] : g_PA[a * HH + (k - HH)];
        CcT[k * 68 + m] = v;
    }
    for (int idx = tid; idx < 64 * 100; idx += 256) {
        int k = idx % 100, o = idx / 100;
        BsT[k * 68 + o] = (o < FO) ? W_A[o * 2 * HH + k] : 0.0f;
    }
    if (tid < 64) bsh[tid] = (tid < FO) ? b_A[tid] : 0.0f;
    __syncthreads();

    const int tm = tid >> 4, tn = tid & 15;
    const int m0 = tm * 4, n0 = tn * 4;
    unsigned long long acc2[2][4];
#pragma unroll
    for (int rp = 0; rp < 2; rp++)
#pragma unroll
        for (int c = 0; c < 4; c++) acc2[rp][c] = 0ull;

#pragma unroll 4
    for (int k = 0; k < 100; k++) {
        ulonglong2 a2 = *(const ulonglong2*)&CcT[k * 68 + m0];
        float4 b4 = *(const float4*)&BsT[k * 68 + n0];
        unsigned long long av[2] = {a2.x, a2.y};
        unsigned long long bd[4] = {dup_(b4.x), dup_(b4.y), dup_(b4.z), dup_(b4.w)};
#pragma unroll
        for (int rp = 0; rp < 2; rp++)
#pragma unroll
            for (int c = 0; c < 4; c++) fma2_(acc2[rp][c], av[rp], bd[c]);
    }
#pragma unroll
    for (int rp = 0; rp < 2; rp++) {
#pragma unroll
        for (int c = 0; c < 4; c++) {
            int o = n0 + c;
            if (o < FO) {
                float2 f2 = unpk_(acc2[rp][c]);
                int a0 = abase + m0 + 2 * rp;
                if (a0 < NA)     outA[(size_t)a0 * FO + o]       = relu_(f2.x + bsh[o]);
                if (a0 + 1 < NA) outA[(size_t)(a0 + 1) * FO + o] = relu_(f2.y + bsh[o]);
            }
        }
    }
}

// =====================================================================
// launch
// =====================================================================
extern "C" void kernel_launch(void* const* d_in, const int* in_sizes, int n_in,
                              void* d_out, int out_size)
{
    const float* af    = (const float*)d_in[0];
    const float* pf    = (const float*)d_in[1];
    const int*   split = (const int*)  d_in[2];
    const int*   atp   = (const int*)  d_in[3];
    const float* W_AA  = (const float*)d_in[4];
    const float* b_AA  = (const float*)d_in[5];
    const float* W_PA  = (const float*)d_in[6];
    const float* b_PA  = (const float*)d_in[7];
    const float* W_A   = (const float*)d_in[8];
    const float* b_A   = (const float*)d_in[9];
    const float* W_AP  = (const float*)d_in[10];
    const float* b_AP  = (const float*)d_in[11];
    const float* W_PP  = (const float*)d_in[12];
    const float* b_PP  = (const float*)d_in[13];
    const float* W_P   = (const float*)d_in[14];
    const float* b_P   = (const float*)d_in[15];
    float* out = (float*)d_out;

    cudaFuncSetAttribute(pair_kernel, cudaFuncAttributeMaxDynamicSharedMemorySize, PAIR_SMEM_BYTES);
    cudaFuncSetAttribute(atom_out_kernel, cudaFuncAttributeMaxDynamicSharedMemorySize, K3_SMEM_BYTES);

    atom_pre_kernel<<<(NA + 63) / 64, 256>>>(af, W_AA, b_AA, W_AP);

    pair_kernel<<<NP / 128, 256, PAIR_SMEM_BYTES>>>(
        pf, split, atp, W_PA, b_PA, W_PP, b_PP, W_P, b_P, b_AP,
        out + (size_t)NA * FO);

    atom_out_kernel<<<(NA + 63) / 64, 256, K3_SMEM_BYTES>>>(W_A, b_A, out);
}

// round 7
// speedup vs baseline: 1.5883x; 1.1179x over previous
#include <cuda_runtime.h>

#define NA 100000
#define NP 3200000
#define FA 75
#define FPR 14
#define HH 50
#define FO 50
#define XS 52   // padded row stride of X1/X2 (50 data + 2 zero), 16B-aligned rows

// ---------------- scratch (device globals; no allocs allowed) ----------------
__device__ float g_AA[NA * HH];   // relu(af @ W_AA^T + b_AA)
__device__ float g_X1[NA * XS];   // af @ W_AP[:, :75]^T   (no bias), cols 50,51 = 0
__device__ float g_X2[NA * XS];   // af @ W_AP[:, 75:]^T   (no bias), cols 50,51 = 0
__device__ float g_PA[NA * HH];   // segment-summed relu(pf @ W_PA^T + b_PA)

__device__ __forceinline__ float relu_(float x) { return fmaxf(x, 0.0f); }

// packed fp32x2 FMA (Blackwell): d = a*b + d, lane-wise on 64-bit pairs
__device__ __forceinline__ void fma2_(unsigned long long& d,
                                      unsigned long long a,
                                      unsigned long long b) {
    asm("fma.rn.f32x2 %0, %1, %2, %0;" : "+l"(d) : "l"(a), "l"(b));
}
__device__ __forceinline__ unsigned long long dup_(float x) {
    unsigned long long r;
    asm("mov.b64 %0, {%1, %1};" : "=l"(r) : "f"(x));
    return r;
}
__device__ __forceinline__ float2 unpk_(unsigned long long v) {
    float2 f;
    asm("mov.b64 {%0, %1}, %2;" : "=f"(f.x), "=f"(f.y) : "l"(v));
    return f;
}

// =====================================================================
// K1: atom-side precompute, merged.  grid = ceil(NA/64), 256 threads.
//   mat 0: g_AA = relu(af @ W_AA^T + b_AA)   (also zeroes g_PA, X pads)
//   mat 1: g_X1 = af @ W1^T     mat 2: g_X2 = af @ W2^T
// =====================================================================
__global__ __launch_bounds__(256) void atom_pre_kernel(
    const float* __restrict__ af,
    const float* __restrict__ W_AA, const float* __restrict__ b_AA,
    const float* __restrict__ W_AP)
{
    __shared__ __align__(16) float AsT[76 * 68];
    __shared__ __align__(16) float BsT[76 * 68];
    __shared__ float bsh[64];

    const int abase = blockIdx.x * 64;
    const int tid = threadIdx.x;

    for (int idx = tid; idx < 64 * 76; idx += 256) {
        int k = idx % 76, m = idx / 76;
        int a = abase + m;
        AsT[k * 68 + m] = (k < FA && a < NA) ? af[a * FA + k] : 0.0f;
    }
    for (int idx = tid; idx < 64 * HH; idx += 256) {
        int m = idx / HH, o = idx % HH;
        int a = abase + m;
        if (a < NA) g_PA[a * HH + o] = 0.0f;
    }
    // zero the X pad columns (50,51)
    for (int idx = tid; idx < 64 * 2; idx += 256) {
        int m = idx >> 1, o = 50 + (idx & 1);
        int a = abase + m;
        if (a < NA) { g_X1[(size_t)a * XS + o] = 0.0f; g_X2[(size_t)a * XS + o] = 0.0f; }
    }
    if (tid < 64) bsh[tid] = (tid < HH) ? b_AA[tid] : 0.0f;

    const int tm = tid >> 4, tn = tid & 15;
    const int m0 = tm * 4, n0 = tn * 4;

    for (int mat = 0; mat < 3; mat++) {
        __syncthreads();
        const float* W; int ws, wo;
        if (mat == 0) { W = W_AA; ws = FA;     wo = 0; }
        else          { W = W_AP; ws = 2 * FA; wo = (mat == 1) ? 0 : FA; }
        for (int idx = tid; idx < 64 * 76; idx += 256) {
            int k = idx % 76, o = idx / 76;
            BsT[k * 68 + o] = (k < FA && o < HH) ? W[o * ws + wo + k] : 0.0f;
        }
        __syncthreads();

        unsigned long long acc2[2][4];
#pragma unroll
        for (int rp = 0; rp < 2; rp++)
#pragma unroll
            for (int c = 0; c < 4; c++) acc2[rp][c] = 0ull;

#pragma unroll 5
        for (int k = 0; k < 75; k++) {
            ulonglong2 a2 = *(const ulonglong2*)&AsT[k * 68 + m0];
            float4 b4 = *(const float4*)&BsT[k * 68 + n0];
            unsigned long long av[2] = {a2.x, a2.y};
            unsigned long long bd[4] = {dup_(b4.x), dup_(b4.y), dup_(b4.z), dup_(b4.w)};
#pragma unroll
            for (int rp = 0; rp < 2; rp++)
#pragma unroll
                for (int c = 0; c < 4; c++) fma2_(acc2[rp][c], av[rp], bd[c]);
        }

        float* dst = (mat == 0) ? g_AA : ((mat == 1) ? g_X1 : g_X2);
        const int ds = (mat == 0) ? HH : XS;
#pragma unroll
        for (int rp = 0; rp < 2; rp++) {
#pragma unroll
            for (int c = 0; c < 4; c++) {
                int o = n0 + c;
                if (o < HH) {
                    float2 f2 = unpk_(acc2[rp][c]);
                    int a0 = abase + m0 + 2 * rp;
                    if (mat == 0) {
                        f2.x = relu_(f2.x + bsh[o]);
                        f2.y = relu_(f2.y + bsh[o]);
                    }
                    if (a0 < NA)     dst[(size_t)a0 * ds + o]       = f2.x;
                    if (a0 + 1 < NA) dst[(size_t)(a0 + 1) * ds + o] = f2.y;
                }
            }
        }
    }
}

// =====================================================================
// K2 (megakernel), 128-pair tiles, 256 threads, 2 blocks/SM.
// Phase order (R2-proven interleave):
//   stage -> P1(PA) -> sync -> P2(segsum) -> sync
//   -> P3(S gathers THEN PP GEMM, same phase: FMA hides gather latency)
//   -> sync -> P4
// =====================================================================
#define CTS 132
#define WTS 68
#define PAIR_SMEM_FLOATS (100*CTS + 100*WTS + 16*CTS + 2*16*WTS + 4*52 + 256 + 132 + 128 + 4)
#define PAIR_SMEM_BYTES  (PAIR_SMEM_FLOATS * 4)

__global__ __launch_bounds__(256, 2) void pair_kernel(
    const float* __restrict__ pf,
    const int*   __restrict__ split,
    const int*   __restrict__ atp,
    const float* __restrict__ W_PA, const float* __restrict__ b_PA,
    const float* __restrict__ W_PP, const float* __restrict__ b_PP,
    const float* __restrict__ W_P,  const float* __restrict__ b_P,
    const float* __restrict__ b_AP,
    float* __restrict__ outP)
{
    extern __shared__ __align__(16) float sm[];
    float* CT   = sm;                       // [100][CTS]
    float* WT   = CT + 100 * CTS;           // [100][WTS]
    float* pfT  = WT + 100 * WTS;           // [16][CTS]
    float* WpaT = pfT + 16 * CTS;           // [16][WTS]
    float* WppT = WpaT + 16 * WTS;          // [16][WTS]
    float* sbAP = WppT + 16 * WTS;          // 52 (pad zeros)
    float* sbPP = sbAP + 52;
    float* sbPA = sbPP + 52;
    float* sbP  = sbPA + 52;
    int* sidx   = (int*)(sbP + 52);         // 256
    int* spsv   = sidx + 256;               // 132
    int* sheads = spsv + 132;               // 128
    int* snh    = sheads + 128;             // 1

    const int p0  = blockIdx.x * 128;
    const int tid = threadIdx.x;

    // ---------------- P0: staging ----------------
    for (int idx = tid; idx < 128 * 16; idx += 256) {
        int kk = idx & 15, p = idx >> 4;
        pfT[kk * CTS + p] = (kk < FPR) ? __ldcs(&pf[(p0 + p) * FPR + kk]) : 0.0f;
    }
    for (int idx = tid; idx < 64 * 100; idx += 256) {
        int k = idx % 100, o = idx / 100;
        WT[k * WTS + o] = (o < FO) ? W_P[o * 2 * HH + k] : 0.0f;
    }
    for (int idx = tid; idx < 64 * 16; idx += 256) {
        int k = idx & 15, o = idx >> 4;
        bool v = (k < FPR && o < HH);
        WpaT[k * WTS + o] = v ? W_PA[o * FPR + k] : 0.0f;
        WppT[k * WTS + o] = v ? W_PP[o * FPR + k] : 0.0f;
    }
    if (tid < 52) {
        sbAP[tid] = (tid < HH) ? b_AP[tid] : 0.0f;
        sbPP[tid] = (tid < HH) ? b_PP[tid] : 0.0f;
        sbPA[tid] = (tid < HH) ? b_PA[tid] : 0.0f;
        sbP[tid]  = (tid < FO) ? b_P[tid]  : 0.0f;
    }
    sidx[tid] = atp[p0 * 2 + tid];
    if (tid < 129) {
        // spsv[0] = -1 ALWAYS: force a run head at t=0 so boundary-crossing
        // runs are accumulated from both tiles (atomics commute).
        spsv[tid] = (tid == 0) ? -1 : split[p0 + tid - 1];
    }
    if (tid == 0) *snh = 0;
    __syncthreads();

    const int tm = tid >> 4, tn = tid & 15;
    const int m0 = tm * 8, n0 = tn * 4;

    // ---------------- P1: PA -> CT rows [0,50) ----------------
    {
        unsigned long long acc2[4][4];
#pragma unroll
        for (int rp = 0; rp < 4; rp++)
#pragma unroll
            for (int c = 0; c < 4; c++) acc2[rp][c] = 0ull;
#pragma unroll
        for (int k = 0; k < FPR; k++) {
            float4 b4 = *(const float4*)&WpaT[k * WTS + n0];
            ulonglong2 a01 = *(const ulonglong2*)&pfT[k * CTS + m0];
            ulonglong2 a23 = *(const ulonglong2*)&pfT[k * CTS + m0 + 4];
            unsigned long long av[4] = {a01.x, a01.y, a23.x, a23.y};
            unsigned long long bd[4] = {dup_(b4.x), dup_(b4.y), dup_(b4.z), dup_(b4.w)};
#pragma unroll
            for (int rp = 0; rp < 4; rp++)
#pragma unroll
                for (int c = 0; c < 4; c++) fma2_(acc2[rp][c], av[rp], bd[c]);
        }
#pragma unroll
        for (int c = 0; c < 4; c++) {
            int o = n0 + c;
            if (o < HH) {
                float b = sbPA[o];
#pragma unroll
                for (int rp = 0; rp < 4; rp++) {
                    float2 f2 = unpk_(acc2[rp][c]);
                    CT[o * CTS + m0 + 2 * rp]     = relu_(f2.x + b);
                    CT[o * CTS + m0 + 2 * rp + 1] = relu_(f2.y + b);
                }
            }
        }
    }
    __syncthreads();

    // ---------------- P2: sorted-run reduce + atomics into g_PA ----------------
    if (tid < 128) {
        if (spsv[tid + 1] != spsv[tid]) {
            int pos = atomicAdd(snh, 1);
            sheads[pos] = tid;
        }
    }
    __syncthreads();
    {
        int nh = *snh;
        for (int t = tid; t < nh * 64; t += 256) {
            int o = t & 63, hi = t >> 6;
            if (o < HH) {
                int h = sheads[hi];
                int seg = spsv[h + 1];
                float s = 0.0f;
                int q = h;
                while (q < 128 && spsv[q + 1] == seg) { s += CT[o * CTS + q]; q++; }
                atomicAdd(&g_PA[seg * HH + o], s);
            }
        }
    }
    __syncthreads();

    // ---------------- P3: S gathers -> CT rows [0,50), then PP GEMM -> rows [50,100) ----
    // Gathers first: LDGs issue early; warps that finish gathering proceed to
    // the PP GEMM, whose FMA work hides other warps' L2 latency (R2-proven).
    // k-inner mapping: consecutive threads walk k within the SAME atom rows.
    for (int idx = tid; idx < 128 * 13; idx += 256) {
        int p = idx / 13, c = idx % 13;
        int k0 = c * 4;
        int i = sidx[2 * p], j = sidx[2 * p + 1];
        float4 a = *(const float4*)(g_X1 + (size_t)i * XS + k0);
        float4 b = *(const float4*)(g_X2 + (size_t)j * XS + k0);
        float4 d = *(const float4*)(g_X1 + (size_t)j * XS + k0);
        float4 e = *(const float4*)(g_X2 + (size_t)i * XS + k0);
        float4 bi = *(const float4*)(sbAP + k0);
        float s0 = relu_(a.x + b.x + bi.x) + relu_(d.x + e.x + bi.x);
        float s1 = relu_(a.y + b.y + bi.y) + relu_(d.y + e.y + bi.y);
        CT[(k0 + 0) * CTS + p] = s0;
        CT[(k0 + 1) * CTS + p] = s1;
        if (c < 12) {   // rows 50,51 belong to PP — chunk 12 writes only k=48,49
            float s2 = relu_(a.z + b.z + bi.z) + relu_(d.z + e.z + bi.z);
            float s3 = relu_(a.w + b.w + bi.w) + relu_(d.w + e.w + bi.w);
            CT[(k0 + 2) * CTS + p] = s2;
            CT[(k0 + 3) * CTS + p] = s3;
        }
    }
    {
        // PP -> CT rows [50,100)
        unsigned long long acc2[4][4];
#pragma unroll
        for (int rp = 0; rp < 4; rp++)
#pragma unroll
            for (int c = 0; c < 4; c++) acc2[rp][c] = 0ull;
#pragma unroll
        for (int k = 0; k < FPR; k++) {
            float4 b4 = *(const float4*)&WppT[k * WTS + n0];
            ulonglong2 a01 = *(const ulonglong2*)&pfT[k * CTS + m0];
            ulonglong2 a23 = *(const ulonglong2*)&pfT[k * CTS + m0 + 4];
            unsigned long long av[4] = {a01.x, a01.y, a23.x, a23.y};
            unsigned long long bd[4] = {dup_(b4.x), dup_(b4.y), dup_(b4.z), dup_(b4.w)};
#pragma unroll
            for (int rp = 0; rp < 4; rp++)
#pragma unroll
                for (int c = 0; c < 4; c++) fma2_(acc2[rp][c], av[rp], bd[c]);
        }
#pragma unroll
        for (int c = 0; c < 4; c++) {
            int o = n0 + c;
            if (o < HH) {
                float b = sbPP[o];
#pragma unroll
                for (int rp = 0; rp < 4; rp++) {
                    float2 f2 = unpk_(acc2[rp][c]);
                    CT[(HH + o) * CTS + m0 + 2 * rp]     = relu_(f2.x + b);
                    CT[(HH + o) * CTS + m0 + 2 * rp + 1] = relu_(f2.y + b);
                }
            }
        }
    }
    __syncthreads();

    // ---------------- P4: P = relu([S|PP] @ W_P^T + b_P), K = 100 ----------------
    {
        unsigned long long acc2[4][4];
#pragma unroll
        for (int rp = 0; rp < 4; rp++)
#pragma unroll
            for (int c = 0; c < 4; c++) acc2[rp][c] = 0ull;
#pragma unroll 4
        for (int k = 0; k < 100; k++) {
            float4 b4 = *(const float4*)&WT[k * WTS + n0];
            ulonglong2 a01 = *(const ulonglong2*)&CT[k * CTS + m0];
            ulonglong2 a23 = *(const ulonglong2*)&CT[k * CTS + m0 + 4];
            unsigned long long av[4] = {a01.x, a01.y, a23.x, a23.y};
            unsigned long long bd[4] = {dup_(b4.x), dup_(b4.y), dup_(b4.z), dup_(b4.w)};
#pragma unroll
            for (int rp = 0; rp < 4; rp++)
#pragma unroll
                for (int c = 0; c < 4; c++) fma2_(acc2[rp][c], av[rp], bd[c]);
        }
        if (n0 < FO) {
            float accf[8][4];
#pragma unroll
            for (int rp = 0; rp < 4; rp++)
#pragma unroll
                for (int c = 0; c < 4; c++) {
                    float2 f2 = unpk_(acc2[rp][c]);
                    accf[2 * rp][c]     = f2.x;
                    accf[2 * rp + 1][c] = f2.y;
                }
            float bb[4];
#pragma unroll
            for (int c = 0; c < 4; c++) bb[c] = sbP[n0 + c];
#pragma unroll
            for (int r = 0; r < 8; r++) {
                size_t p = (size_t)(p0 + m0 + r);
                float v0 = relu_(accf[r][0] + bb[0]);
                float v1 = relu_(accf[r][1] + bb[1]);
                float* dst = &outP[p * FO + n0];
                __stcs((float2*)dst, make_float2(v0, v1));
                if (n0 + 3 < FO) {
                    float v2 = relu_(accf[r][2] + bb[2]);
                    float v3 = relu_(accf[r][3] + bb[3]);
                    __stcs((float2*)(dst + 2), make_float2(v2, v3));
                }
            }
        }
    }
}

// =====================================================================
// K3: A = relu(concat([AA, PAseg]) @ W_A^T + b_A), K = 100
// =====================================================================
#define K3_SMEM_FLOATS (100*68 * 2 + 64)
#define K3_SMEM_BYTES  (K3_SMEM_FLOATS * 4)

__global__ __launch_bounds__(256) void atom_out_kernel(
    const float* __restrict__ W_A, const float* __restrict__ b_A,
    float* __restrict__ outA)
{
    extern __shared__ __align__(16) float sm3[];
    float* CcT = sm3;             // [100][68]
    float* BsT = CcT + 100 * 68;  // [100][68]
    float* bsh = BsT + 100 * 68;  // 64

    const int abase = blockIdx.x * 64;
    const int tid = threadIdx.x;

    for (int idx = tid; idx < 64 * 100; idx += 256) {
        int k = idx % 100, m = idx / 100;
        int a = abase + m;
        float v = 0.0f;
        if (a < NA) v = (k < HH) ? g_AA[a * HH + k] : g_PA[a * HH + (k - HH)];
        CcT[k * 68 + m] = v;
    }
    for (int idx = tid; idx < 64 * 100; idx += 256) {
        int k = idx % 100, o = idx / 100;
        BsT[k * 68 + o] = (o < FO) ? W_A[o * 2 * HH + k] : 0.0f;
    }
    if (tid < 64) bsh[tid] = (tid < FO) ? b_A[tid] : 0.0f;
    __syncthreads();

    const int tm = tid >> 4, tn = tid & 15;
    const int m0 = tm * 4, n0 = tn * 4;
    unsigned long long acc2[2][4];
#pragma unroll
    for (int rp = 0; rp < 2; rp++)
#pragma unroll
        for (int c = 0; c < 4; c++) acc2[rp][c] = 0ull;

#pragma unroll 4
    for (int k = 0; k < 100; k++) {
        ulonglong2 a2 = *(const ulonglong2*)&CcT[k * 68 + m0];
        float4 b4 = *(const float4*)&BsT[k * 68 + n0];
        unsigned long long av[2] = {a2.x, a2.y};
        unsigned long long bd[4] = {dup_(b4.x), dup_(b4.y), dup_(b4.z), dup_(b4.w)};
#pragma unroll
        for (int rp = 0; rp < 2; rp++)
#pragma unroll
            for (int c = 0; c < 4; c++) fma2_(acc2[rp][c], av[rp], bd[c]);
    }
#pragma unroll
    for (int rp = 0; rp < 2; rp++) {
#pragma unroll
        for (int c = 0; c < 4; c++) {
            int o = n0 + c;
            if (o < FO) {
                float2 f2 = unpk_(acc2[rp][c]);
                int a0 = abase + m0 + 2 * rp;
                if (a0 < NA)     outA[(size_t)a0 * FO + o]       = relu_(f2.x + bsh[o]);
                if (a0 + 1 < NA) outA[(size_t)(a0 + 1) * FO + o] = relu_(f2.y + bsh[o]);
            }
        }
    }
}

// =====================================================================
// launch
// =====================================================================
extern "C" void kernel_launch(void* const* d_in, const int* in_sizes, int n_in,
                              void* d_out, int out_size)
{
    const float* af    = (const float*)d_in[0];
    const float* pf    = (const float*)d_in[1];
    const int*   split = (const int*)  d_in[2];
    const int*   atp   = (const int*)  d_in[3];
    const float* W_AA  = (const float*)d_in[4];
    const float* b_AA  = (const float*)d_in[5];
    const float* W_PA  = (const float*)d_in[6];
    const float* b_PA  = (const float*)d_in[7];
    const float* W_A   = (const float*)d_in[8];
    const float* b_A   = (const float*)d_in[9];
    const float* W_AP  = (const float*)d_in[10];
    const float* b_AP  = (const float*)d_in[11];
    const float* W_PP  = (const float*)d_in[12];
    const float* b_PP  = (const float*)d_in[13];
    const float* W_P   = (const float*)d_in[14];
    const float* b_P   = (const float*)d_in[15];
    float* out = (float*)d_out;

    cudaFuncSetAttribute(pair_kernel, cudaFuncAttributeMaxDynamicSharedMemorySize, PAIR_SMEM_BYTES);
    cudaFuncSetAttribute(atom_out_kernel, cudaFuncAttributeMaxDynamicSharedMemorySize, K3_SMEM_BYTES);

    atom_pre_kernel<<<(NA + 63) / 64, 256>>>(af, W_AA, b_AA, W_AP);

    pair_kernel<<<NP / 128, 256, PAIR_SMEM_BYTES>>>(
        pf, split, atp, W_PA, b_PA, W_PP, b_PP, W_P, b_P, b_AP,
        out + (size_t)NA * FO);

    atom_out_kernel<<<(NA + 63) / 64, 256, K3_SMEM_BYTES>>>(W_A, b_A, out);
}

// round 8
// speedup vs baseline: 1.5887x; 1.0003x over previous
#include <cuda_runtime.h>

#define NA 100000
#define NP 3200000
#define FA 75
#define FPR 14
#define HH 50
#define FO 50
#define XS 52   // padded row stride of X1/X2 (50 data + 2 zero), 16B-aligned rows

// ---------------- scratch (device globals; no allocs allowed) ----------------
__device__ float g_AA[NA * HH];   // relu(af @ W_AA^T + b_AA)
__device__ float g_X1[NA * XS];   // af @ W_AP[:, :75]^T   (no bias), cols 50,51 = 0
__device__ float g_X2[NA * XS];   // af @ W_AP[:, 75:]^T   (no bias), cols 50,51 = 0
__device__ float g_PA[NA * HH];   // segment-summed relu(pf @ W_PA^T + b_PA)

__device__ __forceinline__ float relu_(float x) { return fmaxf(x, 0.0f); }

// packed fp32x2 FMA (Blackwell): d = a*b + d, lane-wise on 64-bit pairs
__device__ __forceinline__ void fma2_(unsigned long long& d,
                                      unsigned long long a,
                                      unsigned long long b) {
    asm("fma.rn.f32x2 %0, %1, %2, %0;" : "+l"(d) : "l"(a), "l"(b));
}
__device__ __forceinline__ unsigned long long dup_(float x) {
    unsigned long long r;
    asm("mov.b64 %0, {%1, %1};" : "=l"(r) : "f"(x));
    return r;
}
__device__ __forceinline__ float2 unpk_(unsigned long long v) {
    float2 f;
    asm("mov.b64 {%0, %1}, %2;" : "=f"(f.x), "=f"(f.y) : "l"(v));
    return f;
}

// =====================================================================
// K1: atom-side precompute, merged.  grid = ceil(NA/64), 256 threads.
//   mat 0: g_AA = relu(af @ W_AA^T + b_AA)   (also zeroes g_PA, X pads)
//   mat 1: g_X1 = af @ W1^T     mat 2: g_X2 = af @ W2^T
// =====================================================================
__global__ __launch_bounds__(256) void atom_pre_kernel(
    const float* __restrict__ af,
    const float* __restrict__ W_AA, const float* __restrict__ b_AA,
    const float* __restrict__ W_AP)
{
    __shared__ __align__(16) float AsT[76 * 68];
    __shared__ __align__(16) float BsT[76 * 68];
    __shared__ float bsh[64];

    const int abase = blockIdx.x * 64;
    const int tid = threadIdx.x;

    for (int idx = tid; idx < 64 * 76; idx += 256) {
        int k = idx % 76, m = idx / 76;
        int a = abase + m;
        AsT[k * 68 + m] = (k < FA && a < NA) ? af[a * FA + k] : 0.0f;
    }
    for (int idx = tid; idx < 64 * HH; idx += 256) {
        int m = idx / HH, o = idx % HH;
        int a = abase + m;
        if (a < NA) g_PA[a * HH + o] = 0.0f;
    }
    // zero the X pad columns (50,51)
    for (int idx = tid; idx < 64 * 2; idx += 256) {
        int m = idx >> 1, o = 50 + (idx & 1);
        int a = abase + m;
        if (a < NA) { g_X1[(size_t)a * XS + o] = 0.0f; g_X2[(size_t)a * XS + o] = 0.0f; }
    }
    if (tid < 64) bsh[tid] = (tid < HH) ? b_AA[tid] : 0.0f;

    const int tm = tid >> 4, tn = tid & 15;
    const int m0 = tm * 4, n0 = tn * 4;

    for (int mat = 0; mat < 3; mat++) {
        __syncthreads();
        const float* W; int ws, wo;
        if (mat == 0) { W = W_AA; ws = FA;     wo = 0; }
        else          { W = W_AP; ws = 2 * FA; wo = (mat == 1) ? 0 : FA; }
        for (int idx = tid; idx < 64 * 76; idx += 256) {
            int k = idx % 76, o = idx / 76;
            BsT[k * 68 + o] = (k < FA && o < HH) ? W[o * ws + wo + k] : 0.0f;
        }
        __syncthreads();

        unsigned long long acc2[2][4];
#pragma unroll
        for (int rp = 0; rp < 2; rp++)
#pragma unroll
            for (int c = 0; c < 4; c++) acc2[rp][c] = 0ull;

#pragma unroll 5
        for (int k = 0; k < 75; k++) {
            ulonglong2 a2 = *(const ulonglong2*)&AsT[k * 68 + m0];
            float4 b4 = *(const float4*)&BsT[k * 68 + n0];
            unsigned long long av[2] = {a2.x, a2.y};
            unsigned long long bd[4] = {dup_(b4.x), dup_(b4.y), dup_(b4.z), dup_(b4.w)};
#pragma unroll
            for (int rp = 0; rp < 2; rp++)
#pragma unroll
                for (int c = 0; c < 4; c++) fma2_(acc2[rp][c], av[rp], bd[c]);
        }

        float* dst = (mat == 0) ? g_AA : ((mat == 1) ? g_X1 : g_X2);
        const int ds = (mat == 0) ? HH : XS;
#pragma unroll
        for (int rp = 0; rp < 2; rp++) {
#pragma unroll
            for (int c = 0; c < 4; c++) {
                int o = n0 + c;
                if (o < HH) {
                    float2 f2 = unpk_(acc2[rp][c]);
                    int a0 = abase + m0 + 2 * rp;
                    if (mat == 0) {
                        f2.x = relu_(f2.x + bsh[o]);
                        f2.y = relu_(f2.y + bsh[o]);
                    }
                    if (a0 < NA)     dst[(size_t)a0 * ds + o]       = f2.x;
                    if (a0 + 1 < NA) dst[(size_t)(a0 + 1) * ds + o] = f2.y;
                }
            }
        }
    }
}

// =====================================================================
// K2 (megakernel), 128-pair tiles, 256 threads, 2 blocks/SM.
// Phase order (R2-proven interleave):
//   stage -> P1(PA) -> sync -> P2(segsum) -> sync
//   -> P3(S gathers THEN PP GEMM, same phase: FMA hides gather latency)
//   -> sync -> P4
// =====================================================================
#define CTS 132
#define WTS 68
#define PAIR_SMEM_FLOATS (100*CTS + 100*WTS + 16*CTS + 2*16*WTS + 4*52 + 256 + 132 + 128 + 4)
#define PAIR_SMEM_BYTES  (PAIR_SMEM_FLOATS * 4)

__global__ __launch_bounds__(256, 2) void pair_kernel(
    const float* __restrict__ pf,
    const int*   __restrict__ split,
    const int*   __restrict__ atp,
    const float* __restrict__ W_PA, const float* __restrict__ b_PA,
    const float* __restrict__ W_PP, const float* __restrict__ b_PP,
    const float* __restrict__ W_P,  const float* __restrict__ b_P,
    const float* __restrict__ b_AP,
    float* __restrict__ outP)
{
    extern __shared__ __align__(16) float sm[];
    float* CT   = sm;                       // [100][CTS]
    float* WT   = CT + 100 * CTS;           // [100][WTS]
    float* pfT  = WT + 100 * WTS;           // [16][CTS]
    float* WpaT = pfT + 16 * CTS;           // [16][WTS]
    float* WppT = WpaT + 16 * WTS;          // [16][WTS]
    float* sbAP = WppT + 16 * WTS;          // 52 (pad zeros)
    float* sbPP = sbAP + 52;
    float* sbPA = sbPP + 52;
    float* sbP  = sbPA + 52;
    int* sidx   = (int*)(sbP + 52);         // 256
    int* spsv   = sidx + 256;               // 132
    int* sheads = spsv + 132;               // 128
    int* snh    = sheads + 128;             // 1

    const int p0  = blockIdx.x * 128;
    const int tid = threadIdx.x;

    // ---------------- P0: staging ----------------
    for (int idx = tid; idx < 128 * 16; idx += 256) {
        int kk = idx & 15, p = idx >> 4;
        pfT[kk * CTS + p] = (kk < FPR) ? __ldcs(&pf[(p0 + p) * FPR + kk]) : 0.0f;
    }
    for (int idx = tid; idx < 64 * 100; idx += 256) {
        int k = idx % 100, o = idx / 100;
        WT[k * WTS + o] = (o < FO) ? W_P[o * 2 * HH + k] : 0.0f;
    }
    for (int idx = tid; idx < 64 * 16; idx += 256) {
        int k = idx & 15, o = idx >> 4;
        bool v = (k < FPR && o < HH);
        WpaT[k * WTS + o] = v ? W_PA[o * FPR + k] : 0.0f;
        WppT[k * WTS + o] = v ? W_PP[o * FPR + k] : 0.0f;
    }
    if (tid < 52) {
        sbAP[tid] = (tid < HH) ? b_AP[tid] : 0.0f;
        sbPP[tid] = (tid < HH) ? b_PP[tid] : 0.0f;
        sbPA[tid] = (tid < HH) ? b_PA[tid] : 0.0f;
        sbP[tid]  = (tid < FO) ? b_P[tid]  : 0.0f;
    }
    sidx[tid] = atp[p0 * 2 + tid];
    if (tid < 129) {
        // spsv[0] = -1 ALWAYS: force a run head at t=0 so boundary-crossing
        // runs are accumulated from both tiles (atomics commute).
        spsv[tid] = (tid == 0) ? -1 : split[p0 + tid - 1];
    }
    if (tid == 0) *snh = 0;
    __syncthreads();

    const int tm = tid >> 4, tn = tid & 15;
    const int m0 = tm * 8, n0 = tn * 4;

    // ---------------- P1: PA -> CT rows [0,50) ----------------
    {
        unsigned long long acc2[4][4];
#pragma unroll
        for (int rp = 0; rp < 4; rp++)
#pragma unroll
            for (int c = 0; c < 4; c++) acc2[rp][c] = 0ull;
#pragma unroll
        for (int k = 0; k < FPR; k++) {
            float4 b4 = *(const float4*)&WpaT[k * WTS + n0];
            ulonglong2 a01 = *(const ulonglong2*)&pfT[k * CTS + m0];
            ulonglong2 a23 = *(const ulonglong2*)&pfT[k * CTS + m0 + 4];
            unsigned long long av[4] = {a01.x, a01.y, a23.x, a23.y};
            unsigned long long bd[4] = {dup_(b4.x), dup_(b4.y), dup_(b4.z), dup_(b4.w)};
#pragma unroll
            for (int rp = 0; rp < 4; rp++)
#pragma unroll
                for (int c = 0; c < 4; c++) fma2_(acc2[rp][c], av[rp], bd[c]);
        }
#pragma unroll
        for (int c = 0; c < 4; c++) {
            int o = n0 + c;
            if (o < HH) {
                float b = sbPA[o];
#pragma unroll
                for (int rp = 0; rp < 4; rp++) {
                    float2 f2 = unpk_(acc2[rp][c]);
                    CT[o * CTS + m0 + 2 * rp]     = relu_(f2.x + b);
                    CT[o * CTS + m0 + 2 * rp + 1] = relu_(f2.y + b);
                }
            }
        }
    }
    __syncthreads();

    // ---------------- P2: sorted-run reduce + atomics into g_PA ----------------
    if (tid < 128) {
        if (spsv[tid + 1] != spsv[tid]) {
            int pos = atomicAdd(snh, 1);
            sheads[pos] = tid;
        }
    }
    __syncthreads();
    {
        int nh = *snh;
        for (int t = tid; t < nh * 64; t += 256) {
            int o = t & 63, hi = t >> 6;
            if (o < HH) {
                int h = sheads[hi];
                int seg = spsv[h + 1];
                float s = 0.0f;
                int q = h;
                while (q < 128 && spsv[q + 1] == seg) { s += CT[o * CTS + q]; q++; }
                atomicAdd(&g_PA[seg * HH + o], s);
            }
        }
    }
    __syncthreads();

    // ---------------- P3: S gathers -> CT rows [0,50), then PP GEMM -> rows [50,100) ----
    // Gathers first: LDGs issue early; warps that finish gathering proceed to
    // the PP GEMM, whose FMA work hides other warps' L2 latency (R2-proven).
    // k-inner mapping: consecutive threads walk k within the SAME atom rows.
    for (int idx = tid; idx < 128 * 13; idx += 256) {
        int p = idx / 13, c = idx % 13;
        int k0 = c * 4;
        int i = sidx[2 * p], j = sidx[2 * p + 1];
        float4 a = *(const float4*)(g_X1 + (size_t)i * XS + k0);
        float4 b = *(const float4*)(g_X2 + (size_t)j * XS + k0);
        float4 d = *(const float4*)(g_X1 + (size_t)j * XS + k0);
        float4 e = *(const float4*)(g_X2 + (size_t)i * XS + k0);
        float4 bi = *(const float4*)(sbAP + k0);
        float s0 = relu_(a.x + b.x + bi.x) + relu_(d.x + e.x + bi.x);
        float s1 = relu_(a.y + b.y + bi.y) + relu_(d.y + e.y + bi.y);
        CT[(k0 + 0) * CTS + p] = s0;
        CT[(k0 + 1) * CTS + p] = s1;
        if (c < 12) {   // rows 50,51 belong to PP — chunk 12 writes only k=48,49
            float s2 = relu_(a.z + b.z + bi.z) + relu_(d.z + e.z + bi.z);
            float s3 = relu_(a.w + b.w + bi.w) + relu_(d.w + e.w + bi.w);
            CT[(k0 + 2) * CTS + p] = s2;
            CT[(k0 + 3) * CTS + p] = s3;
        }
    }
    {
        // PP -> CT rows [50,100)
        unsigned long long acc2[4][4];
#pragma unroll
        for (int rp = 0; rp < 4; rp++)
#pragma unroll
            for (int c = 0; c < 4; c++) acc2[rp][c] = 0ull;
#pragma unroll
        for (int k = 0; k < FPR; k++) {
            float4 b4 = *(const float4*)&WppT[k * WTS + n0];
            ulonglong2 a01 = *(const ulonglong2*)&pfT[k * CTS + m0];
            ulonglong2 a23 = *(const ulonglong2*)&pfT[k * CTS + m0 + 4];
            unsigned long long av[4] = {a01.x, a01.y, a23.x, a23.y};
            unsigned long long bd[4] = {dup_(b4.x), dup_(b4.y), dup_(b4.z), dup_(b4.w)};
#pragma unroll
            for (int rp = 0; rp < 4; rp++)
#pragma unroll
                for (int c = 0; c < 4; c++) fma2_(acc2[rp][c], av[rp], bd[c]);
        }
#pragma unroll
        for (int c = 0; c < 4; c++) {
            int o = n0 + c;
            if (o < HH) {
                float b = sbPP[o];
#pragma unroll
                for (int rp = 0; rp < 4; rp++) {
                    float2 f2 = unpk_(acc2[rp][c]);
                    CT[(HH + o) * CTS + m0 + 2 * rp]     = relu_(f2.x + b);
                    CT[(HH + o) * CTS + m0 + 2 * rp + 1] = relu_(f2.y + b);
                }
            }
        }
    }
    __syncthreads();

    // ---------------- P4: P = relu([S|PP] @ W_P^T + b_P), K = 100 ----------------
    {
        unsigned long long acc2[4][4];
#pragma unroll
        for (int rp = 0; rp < 4; rp++)
#pragma unroll
            for (int c = 0; c < 4; c++) acc2[rp][c] = 0ull;
#pragma unroll 4
        for (int k = 0; k < 100; k++) {
            float4 b4 = *(const float4*)&WT[k * WTS + n0];
            ulonglong2 a01 = *(const ulonglong2*)&CT[k * CTS + m0];
            ulonglong2 a23 = *(const ulonglong2*)&CT[k * CTS + m0 + 4];
            unsigned long long av[4] = {a01.x, a01.y, a23.x, a23.y};
            unsigned long long bd[4] = {dup_(b4.x), dup_(b4.y), dup_(b4.z), dup_(b4.w)};
#pragma unroll
            for (int rp = 0; rp < 4; rp++)
#pragma unroll
                for (int c = 0; c < 4; c++) fma2_(acc2[rp][c], av[rp], bd[c]);
        }
        if (n0 < FO) {
            float accf[8][4];
#pragma unroll
            for (int rp = 0; rp < 4; rp++)
#pragma unroll
                for (int c = 0; c < 4; c++) {
                    float2 f2 = unpk_(acc2[rp][c]);
                    accf[2 * rp][c]     = f2.x;
                    accf[2 * rp + 1][c] = f2.y;
                }
            float bb[4];
#pragma unroll
            for (int c = 0; c < 4; c++) bb[c] = sbP[n0 + c];
#pragma unroll
            for (int r = 0; r < 8; r++) {
                size_t p = (size_t)(p0 + m0 + r);
                float v0 = relu_(accf[r][0] + bb[0]);
                float v1 = relu_(accf[r][1] + bb[1]);
                float* dst = &outP[p * FO + n0];
                __stcs((float2*)dst, make_float2(v0, v1));
                if (n0 + 3 < FO) {
                    float v2 = relu_(accf[r][2] + bb[2]);
                    float v3 = relu_(accf[r][3] + bb[3]);
                    __stcs((float2*)(dst + 2), make_float2(v2, v3));
                }
            }
        }
    }
}

// =====================================================================
// K3: A = relu(concat([AA, PAseg]) @ W_A^T + b_A), K = 100
// =====================================================================
#define K3_SMEM_FLOATS (100*68 * 2 + 64)
#define K3_SMEM_BYTES  (K3_SMEM_FLOATS * 4)

__global__ __launch_bounds__(256) void atom_out_kernel(
    const float* __restrict__ W_A, const float* __restrict__ b_A,
    float* __restrict__ outA)
{
    extern __shared__ __align__(16) float sm3[];
    float* CcT = sm3;             // [100][68]
    float* BsT = CcT + 100 * 68;  // [100][68]
    float* bsh = BsT + 100 * 68;  // 64

    const int abase = blockIdx.x * 64;
    const int tid = threadIdx.x;

    for (int idx = tid; idx < 64 * 100; idx += 256) {
        int k = idx % 100, m = idx / 100;
        int a = abase + m;
        float v = 0.0f;
        if (a < NA) v = (k < HH) ? g_AA[a * HH + k] : g_PA[a * HH + (k - HH)];
        CcT[k * 68 + m] = v;
    }
    for (int idx = tid; idx < 64 * 100; idx += 256) {
        int k = idx % 100, o = idx / 100;
        BsT[k * 68 + o] = (o < FO) ? W_A[o * 2 * HH + k] : 0.0f;
    }
    if (tid < 64) bsh[tid] = (tid < FO) ? b_A[tid] : 0.0f;
    __syncthreads();

    const int tm = tid >> 4, tn = tid & 15;
    const int m0 = tm * 4, n0 = tn * 4;
    unsigned long long acc2[2][4];
#pragma unroll
    for (int rp = 0; rp < 2; rp++)
#pragma unroll
        for (int c = 0; c < 4; c++) acc2[rp][c] = 0ull;

#pragma unroll 4
    for (int k = 0; k < 100; k++) {
        ulonglong2 a2 = *(const ulonglong2*)&CcT[k * 68 + m0];
        float4 b4 = *(const float4*)&BsT[k * 68 + n0];
        unsigned long long av[2] = {a2.x, a2.y};
        unsigned long long bd[4] = {dup_(b4.x), dup_(b4.y), dup_(b4.z), dup_(b4.w)};
#pragma unroll
        for (int rp = 0; rp < 2; rp++)
#pragma unroll
            for (int c = 0; c < 4; c++) fma2_(acc2[rp][c], av[rp], bd[c]);
    }
#pragma unroll
    for (int rp = 0; rp < 2; rp++) {
#pragma unroll
        for (int c = 0; c < 4; c++) {
            int o = n0 + c;
            if (o < FO) {
                float2 f2 = unpk_(acc2[rp][c]);
                int a0 = abase + m0 + 2 * rp;
                if (a0 < NA)     outA[(size_t)a0 * FO + o]       = relu_(f2.x + bsh[o]);
                if (a0 + 1 < NA) outA[(size_t)(a0 + 1) * FO + o] = relu_(f2.y + bsh[o]);
            }
        }
    }
}

// =====================================================================
// launch
// =====================================================================
extern "C" void kernel_launch(void* const* d_in, const int* in_sizes, int n_in,
                              void* d_out, int out_size)
{
    const float* af    = (const float*)d_in[0];
    const float* pf    = (const float*)d_in[1];
    const int*   split = (const int*)  d_in[2];
    const int*   atp   = (const int*)  d_in[3];
    const float* W_AA  = (const float*)d_in[4];
    const float* b_AA  = (const float*)d_in[5];
    const float* W_PA  = (const float*)d_in[6];
    const float* b_PA  = (const float*)d_in[7];
    const float* W_A   = (const float*)d_in[8];
    const float* b_A   = (const float*)d_in[9];
    const float* W_AP  = (const float*)d_in[10];
    const float* b_AP  = (const float*)d_in[11];
    const float* W_PP  = (const float*)d_in[12];
    const float* b_PP  = (const float*)d_in[13];
    const float* W_P   = (const float*)d_in[14];
    const float* b_P   = (const float*)d_in[15];
    float* out = (float*)d_out;

    cudaFuncSetAttribute(pair_kernel, cudaFuncAttributeMaxDynamicSharedMemorySize, PAIR_SMEM_BYTES);
    cudaFuncSetAttribute(atom_out_kernel, cudaFuncAttributeMaxDynamicSharedMemorySize, K3_SMEM_BYTES);

    atom_pre_kernel<<<(NA + 63) / 64, 256>>>(af, W_AA, b_AA, W_AP);

    pair_kernel<<<NP / 128, 256, PAIR_SMEM_BYTES>>>(
        pf, split, atp, W_PA, b_PA, W_PP, b_PP, W_P, b_P, b_AP,
        out + (size_t)NA * FO);

    atom_out_kernel<<<(NA + 63) / 64, 256, K3_SMEM_BYTES>>>(W_A, b_A, out);
}

// round 9
// speedup vs baseline: 1.6636x; 1.0472x over previous
#include <cuda_runtime.h>

#define NA 100000
#define NP 3200000
#define FA 75
#define FPR 14
#define HH 50
#define FO 50
#define XS 52
typedef unsigned long long ull;

__device__ float g_AA[NA * HH];
__device__ float g_X1[NA * XS];
__device__ float g_X2[NA * XS];
__device__ float g_PA[NA * HH];

__device__ __forceinline__ float relu_(float x) { return fmaxf(x, 0.0f); }
__device__ __forceinline__ void fma2_(ull& d, ull a, ull b) {
    asm("fma.rn.f32x2 %0, %1, %2, %0;" : "+l"(d) : "l"(a), "l"(b));
}
__device__ __forceinline__ ull dup_(float x) {
    ull r; asm("mov.b64 %0, {%1, %1};" : "=l"(r) : "f"(x)); return r;
}
__device__ __forceinline__ float2 unpk_(ull v) {
    float2 f; asm("mov.b64 {%0, %1}, %2;" : "=f"(f.x), "=f"(f.y) : "l"(v)); return f;
}

// ============ K1: atom precompute (unchanged from R7) ============
__global__ __launch_bounds__(256) void atom_pre_kernel(
    const float* __restrict__ af,
    const float* __restrict__ W_AA, const float* __restrict__ b_AA,
    const float* __restrict__ W_AP)
{
    __shared__ __align__(16) float AsT[76 * 68];
    __shared__ __align__(16) float BsT[76 * 68];
    __shared__ float bsh[64];
    const int abase = blockIdx.x * 64;
    const int tid = threadIdx.x;

    for (int idx = tid; idx < 64 * 76; idx += 256) {
        int k = idx % 76, m = idx / 76;
        int a = abase + m;
        AsT[k * 68 + m] = (k < FA && a < NA) ? af[a * FA + k] : 0.0f;
    }
    for (int idx = tid; idx < 64 * HH; idx += 256) {
        int m = idx / HH, o = idx % HH;
        int a = abase + m;
        if (a < NA) g_PA[a * HH + o] = 0.0f;
    }
    for (int idx = tid; idx < 64 * 2; idx += 256) {
        int m = idx >> 1, o = 50 + (idx & 1);
        int a = abase + m;
        if (a < NA) { g_X1[(size_t)a * XS + o] = 0.0f; g_X2[(size_t)a * XS + o] = 0.0f; }
    }
    if (tid < 64) bsh[tid] = (tid < HH) ? b_AA[tid] : 0.0f;

    const int tm = tid >> 4, tn = tid & 15;
    const int m0 = tm * 4, n0 = tn * 4;

    for (int mat = 0; mat < 3; mat++) {
        __syncthreads();
        const float* W; int ws, wo;
        if (mat == 0) { W = W_AA; ws = FA;     wo = 0; }
        else          { W = W_AP; ws = 2 * FA; wo = (mat == 1) ? 0 : FA; }
        for (int idx = tid; idx < 64 * 76; idx += 256) {
            int k = idx % 76, o = idx / 76;
            BsT[k * 68 + o] = (k < FA && o < HH) ? W[o * ws + wo + k] : 0.0f;
        }
        __syncthreads();

        ull acc2[2][4];
#pragma unroll
        for (int rp = 0; rp < 2; rp++)
#pragma unroll
            for (int c = 0; c < 4; c++) acc2[rp][c] = 0ull;
#pragma unroll 5
        for (int k = 0; k < 75; k++) {
            ulonglong2 a2 = *(const ulonglong2*)&AsT[k * 68 + m0];
            float4 b4 = *(const float4*)&BsT[k * 68 + n0];
            ull av[2] = {a2.x, a2.y};
            ull bd[4] = {dup_(b4.x), dup_(b4.y), dup_(b4.z), dup_(b4.w)};
#pragma unroll
            for (int rp = 0; rp < 2; rp++)
#pragma unroll
                for (int c = 0; c < 4; c++) fma2_(acc2[rp][c], av[rp], bd[c]);
        }
        float* dst = (mat == 0) ? g_AA : ((mat == 1) ? g_X1 : g_X2);
        const int ds = (mat == 0) ? HH : XS;
#pragma unroll
        for (int rp = 0; rp < 2; rp++) {
#pragma unroll
            for (int c = 0; c < 4; c++) {
                int o = n0 + c;
                if (o < HH) {
                    float2 f2 = unpk_(acc2[rp][c]);
                    int a0 = abase + m0 + 2 * rp;
                    if (mat == 0) { f2.x = relu_(f2.x + bsh[o]); f2.y = relu_(f2.y + bsh[o]); }
                    if (a0 < NA)     dst[(size_t)a0 * ds + o]       = f2.x;
                    if (a0 + 1 < NA) dst[(size_t)(a0 + 1) * ds + o] = f2.y;
                }
            }
        }
    }
}

// ============ K2: persistent pair megakernel ============
// 64-pair tiles, 256 threads, 3 CTAs/SM (~68KB smem), weights staged once.
// Per tile: stage(pfT/idx/psv) -> sync -> P1(PA) -> sync -> P2(segsum)
//           -> sync -> P3(S gathers + PP) -> sync -> P4 -> (loop)
#define NT (NP / 64)          // 50000 tiles
#define GRID_P 444            // 3 CTAs/SM * 148 SMs
// smem floats: CT 6800, WT 6800, pfT 1088, WpaT 1088, WppT 1088, bias 208,
//              idx 128, psv 68, heads 64, nh 4  -> 17336 floats = 67.7KB
#define PAIR_SMEM_BYTES (17336 * 4)

__global__ __launch_bounds__(256, 3) void pair_kernel(
    const float* __restrict__ pf,
    const int*   __restrict__ split,
    const int*   __restrict__ atp,
    const float* __restrict__ W_PA, const float* __restrict__ b_PA,
    const float* __restrict__ W_PP, const float* __restrict__ b_PP,
    const float* __restrict__ W_P,  const float* __restrict__ b_P,
    const float* __restrict__ b_AP,
    float* __restrict__ outP)
{
    extern __shared__ __align__(16) float sm[];
    float* CT   = sm;              // [100][68]
    float* WT   = CT + 6800;       // [100][68]
    float* pfT  = WT + 6800;       // [16][68]
    float* WpaT = pfT + 1088;      // [16][68]
    float* WppT = WpaT + 1088;     // [16][68]
    float* sbAP = WppT + 1088;     // 52
    float* sbPP = sbAP + 52;
    float* sbPA = sbPP + 52;
    float* sbP  = sbPA + 52;
    int* sidx   = (int*)(sbP + 52);   // 128
    int* spsv   = sidx + 128;         // 68
    int* sheads = spsv + 68;          // 64
    int* snh    = sheads + 64;        // 1

    const int tid = threadIdx.x;
    const int tm = tid >> 4, tn = tid & 15;
    const int m0 = tm * 4, n0 = tn * 4;

    // ---- one-time weight staging ----
    for (int idx = tid; idx < 6400; idx += 256) {
        int k = idx % 100, o = idx / 100;
        WT[k * 68 + o] = (o < FO) ? W_P[o * 2 * HH + k] : 0.0f;
    }
    for (int idx = tid; idx < 1024; idx += 256) {
        int k = idx & 15, o = idx >> 4;
        bool v = (k < FPR && o < HH);
        WpaT[k * 68 + o] = v ? W_PA[o * FPR + k] : 0.0f;
        WppT[k * 68 + o] = v ? W_PP[o * FPR + k] : 0.0f;
    }
    if (tid < 52) {
        sbAP[tid] = (tid < HH) ? b_AP[tid] : 0.0f;
        sbPP[tid] = (tid < HH) ? b_PP[tid] : 0.0f;
        sbPA[tid] = (tid < HH) ? b_PA[tid] : 0.0f;
        sbP[tid]  = (tid < FO) ? b_P[tid]  : 0.0f;
    }

    for (int t = blockIdx.x; t < NT; t += GRID_P) {
        const int p0 = t * 64;

        // ---- stage tile inputs (prev P4 reads only CT/WT: safe) ----
        for (int idx = tid; idx < 1024; idx += 256) {
            int kk = idx & 15, p = idx >> 4;
            pfT[kk * 68 + p] = (kk < FPR) ? __ldcs(&pf[(size_t)(p0 + p) * FPR + kk]) : 0.0f;
        }
        if (tid < 128) sidx[tid] = atp[(size_t)p0 * 2 + tid];
        if (tid < 65)  spsv[tid] = (tid == 0) ? -1 : split[p0 + tid - 1]; // forced head at t=0
        if (tid == 0)  *snh = 0;
        __syncthreads();

        // ---- P1: PA -> CT rows [0,50) ----
        {
            ull acc2[2][4];
#pragma unroll
            for (int rp = 0; rp < 2; rp++)
#pragma unroll
                for (int c = 0; c < 4; c++) acc2[rp][c] = 0ull;
#pragma unroll
            for (int k = 0; k < FPR; k++) {
                float4 b4 = *(const float4*)&WpaT[k * 68 + n0];
                ulonglong2 a2 = *(const ulonglong2*)&pfT[k * 68 + m0];
                ull av[2] = {a2.x, a2.y};
                ull bd[4] = {dup_(b4.x), dup_(b4.y), dup_(b4.z), dup_(b4.w)};
#pragma unroll
                for (int rp = 0; rp < 2; rp++)
#pragma unroll
                    for (int c = 0; c < 4; c++) fma2_(acc2[rp][c], av[rp], bd[c]);
            }
#pragma unroll
            for (int c = 0; c < 4; c++) {
                int o = n0 + c;
                if (o < HH) {
                    float b = sbPA[o];
#pragma unroll
                    for (int rp = 0; rp < 2; rp++) {
                        float2 f2 = unpk_(acc2[rp][c]);
                        *(float2*)&CT[o * 68 + m0 + 2 * rp] =
                            make_float2(relu_(f2.x + b), relu_(f2.y + b));
                    }
                }
            }
        }
        __syncthreads();

        // ---- P2: sorted-run reduce + atomics ----
        if (tid < 64) {
            if (spsv[tid + 1] != spsv[tid]) {
                int pos = atomicAdd(snh, 1);
                sheads[pos] = tid;
            }
        }
        __syncthreads();
        {
            int nh = *snh;
            for (int w = tid; w < nh * 64; w += 256) {
                int o = w & 63, hi = w >> 6;
                if (o < HH) {
                    int h = sheads[hi];
                    int seg = spsv[h + 1];
                    float s = 0.0f;
                    int q = h;
                    while (q < 64 && spsv[q + 1] == seg) { s += CT[o * 68 + q]; q++; }
                    atomicAdd(&g_PA[(size_t)seg * HH + o], s);
                }
            }
        }
        __syncthreads();

        // ---- P3: S gathers -> CT rows [0,50), then PP -> rows [50,100) ----
        for (int idx = tid; idx < 64 * 13; idx += 256) {
            int p = idx / 13, c = idx % 13;
            int k0 = c * 4;
            int i = sidx[2 * p], j = sidx[2 * p + 1];
            float4 a = *(const float4*)(g_X1 + (size_t)i * XS + k0);
            float4 b = *(const float4*)(g_X2 + (size_t)j * XS + k0);
            float4 d = *(const float4*)(g_X1 + (size_t)j * XS + k0);
            float4 e = *(const float4*)(g_X2 + (size_t)i * XS + k0);
            float4 bi = *(const float4*)(sbAP + k0);
            CT[(k0 + 0) * 68 + p] = relu_(a.x + b.x + bi.x) + relu_(d.x + e.x + bi.x);
            CT[(k0 + 1) * 68 + p] = relu_(a.y + b.y + bi.y) + relu_(d.y + e.y + bi.y);
            if (c < 12) {
                CT[(k0 + 2) * 68 + p] = relu_(a.z + b.z + bi.z) + relu_(d.z + e.z + bi.z);
                CT[(k0 + 3) * 68 + p] = relu_(a.w + b.w + bi.w) + relu_(d.w + e.w + bi.w);
            }
        }
        {
            ull acc2[2][4];
#pragma unroll
            for (int rp = 0; rp < 2; rp++)
#pragma unroll
                for (int c = 0; c < 4; c++) acc2[rp][c] = 0ull;
#pragma unroll
            for (int k = 0; k < FPR; k++) {
                float4 b4 = *(const float4*)&WppT[k * 68 + n0];
                ulonglong2 a2 = *(const ulonglong2*)&pfT[k * 68 + m0];
                ull av[2] = {a2.x, a2.y};
                ull bd[4] = {dup_(b4.x), dup_(b4.y), dup_(b4.z), dup_(b4.w)};
#pragma unroll
                for (int rp = 0; rp < 2; rp++)
#pragma unroll
                    for (int c = 0; c < 4; c++) fma2_(acc2[rp][c], av[rp], bd[c]);
            }
#pragma unroll
            for (int c = 0; c < 4; c++) {
                int o = n0 + c;
                if (o < HH) {
                    float b = sbPP[o];
#pragma unroll
                    for (int rp = 0; rp < 2; rp++) {
                        float2 f2 = unpk_(acc2[rp][c]);
                        *(float2*)&CT[(HH + o) * 68 + m0 + 2 * rp] =
                            make_float2(relu_(f2.x + b), relu_(f2.y + b));
                    }
                }
            }
        }
        __syncthreads();

        // ---- P4: P = relu([S|PP] @ W_P^T + b_P), K=100 ----
        {
            ull acc2[2][4];
#pragma unroll
            for (int rp = 0; rp < 2; rp++)
#pragma unroll
                for (int c = 0; c < 4; c++) acc2[rp][c] = 0ull;
#pragma unroll 4
            for (int k = 0; k < 100; k++) {
                float4 b4 = *(const float4*)&WT[k * 68 + n0];
                ulonglong2 a2 = *(const ulonglong2*)&CT[k * 68 + m0];
                ull av[2] = {a2.x, a2.y};
                ull bd[4] = {dup_(b4.x), dup_(b4.y), dup_(b4.z), dup_(b4.w)};
#pragma unroll
                for (int rp = 0; rp < 2; rp++)
#pragma unroll
                    for (int c = 0; c < 4; c++) fma2_(acc2[rp][c], av[rp], bd[c]);
            }
            if (n0 < FO) {
                float accf[4][4];
#pragma unroll
                for (int rp = 0; rp < 2; rp++)
#pragma unroll
                    for (int c = 0; c < 4; c++) {
                        float2 f2 = unpk_(acc2[rp][c]);
                        accf[2 * rp][c] = f2.x;
                        accf[2 * rp + 1][c] = f2.y;
                    }
                float bb[4];
#pragma unroll
                for (int c = 0; c < 4; c++) bb[c] = sbP[n0 + c];
                bool full = (n0 + 3 < FO);
#pragma unroll
                for (int r = 0; r < 4; r++) {
                    size_t p = (size_t)(p0 + m0 + r);
                    float* dst = &outP[p * FO + n0];
                    __stcs((float2*)dst,
                           make_float2(relu_(accf[r][0] + bb[0]), relu_(accf[r][1] + bb[1])));
                    if (full)
                        __stcs((float2*)(dst + 2),
                               make_float2(relu_(accf[r][2] + bb[2]), relu_(accf[r][3] + bb[3])));
                }
            }
        }
        __syncthreads();
    }
}

// ============ K3: A-output (unchanged) ============
#define K3_SMEM_BYTES ((100*68*2 + 64) * 4)
__global__ __launch_bounds__(256) void atom_out_kernel(
    const float* __restrict__ W_A, const float* __restrict__ b_A,
    float* __restrict__ outA)
{
    extern __shared__ __align__(16) float sm3[];
    float* CcT = sm3;
    float* BsT = CcT + 100 * 68;
    float* bsh = BsT + 100 * 68;
    const int abase = blockIdx.x * 64;
    const int tid = threadIdx.x;

    for (int idx = tid; idx < 64 * 100; idx += 256) {
        int k = idx % 100, m = idx / 100;
        int a = abase + m;
        float v = 0.0f;
        if (a < NA) v = (k < HH) ? g_AA[a * HH + k] : g_PA[a * HH + (k - HH)];
        CcT[k * 68 + m] = v;
    }
    for (int idx = tid; idx < 64 * 100; idx += 256) {
        int k = idx % 100, o = idx / 100;
        BsT[k * 68 + o] = (o < FO) ? W_A[o * 2 * HH + k] : 0.0f;
    }
    if (tid < 64) bsh[tid] = (tid < FO) ? b_A[tid] : 0.0f;
    __syncthreads();

    const int tm = tid >> 4, tn = tid & 15;
    const int m0 = tm * 4, n0 = tn * 4;
    ull acc2[2][4];
#pragma unroll
    for (int rp = 0; rp < 2; rp++)
#pragma unroll
        for (int c = 0; c < 4; c++) acc2[rp][c] = 0ull;
#pragma unroll 4
    for (int k = 0; k < 100; k++) {
        ulonglong2 a2 = *(const ulonglong2*)&CcT[k * 68 + m0];
        float4 b4 = *(const float4*)&BsT[k * 68 + n0];
        ull av[2] = {a2.x, a2.y};
        ull bd[4] = {dup_(b4.x), dup_(b4.y), dup_(b4.z), dup_(b4.w)};
#pragma unroll
        for (int rp = 0; rp < 2; rp++)
#pragma unroll
            for (int c = 0; c < 4; c++) fma2_(acc2[rp][c], av[rp], bd[c]);
    }
#pragma unroll
    for (int rp = 0; rp < 2; rp++) {
#pragma unroll
        for (int c = 0; c < 4; c++) {
            int o = n0 + c;
            if (o < FO) {
                float2 f2 = unpk_(acc2[rp][c]);
                int a0 = abase + m0 + 2 * rp;
                if (a0 < NA)     outA[(size_t)a0 * FO + o]       = relu_(f2.x + bsh[o]);
                if (a0 + 1 < NA) outA[(size_t)(a0 + 1) * FO + o] = relu_(f2.y + bsh[o]);
            }
        }
    }
}

extern "C" void kernel_launch(void* const* d_in, const int* in_sizes, int n_in,
                              void* d_out, int out_size)
{
    const float* af    = (const float*)d_in[0];
    const float* pf    = (const float*)d_in[1];
    const int*   split = (const int*)  d_in[2];
    const int*   atp   = (const int*)  d_in[3];
    const float* W_AA  = (const float*)d_in[4];
    const float* b_AA  = (const float*)d_in[5];
    const float* W_PA  = (const float*)d_in[6];
    const float* b_PA  = (const float*)d_in[7];
    const float* W_A   = (const float*)d_in[8];
    const float* b_A   = (const float*)d_in[9];
    const float* W_AP  = (const float*)d_in[10];
    const float* b_AP  = (const float*)d_in[11];
    const float* W_PP  = (const float*)d_in[12];
    const float* b_PP  = (const float*)d_in[13];
    const float* W_P   = (const float*)d_in[14];
    const float* b_P   = (const float*)d_in[15];
    float* out = (float*)d_out;

    cudaFuncSetAttribute(pair_kernel, cudaFuncAttributeMaxDynamicSharedMemorySize, PAIR_SMEM_BYTES);
    cudaFuncSetAttribute(atom_out_kernel, cudaFuncAttributeMaxDynamicSharedMemorySize, K3_SMEM_BYTES);

    atom_pre_kernel<<<(NA + 63) / 64, 256>>>(af, W_AA, b_AA, W_AP);

    pair_kernel<<<GRID_P, 256, PAIR_SMEM_BYTES>>>(
        pf, split, atp, W_PA, b_PA, W_PP, b_PP, W_P, b_P, b_AP,
        out + (size_t)NA * FO);

    atom_out_kernel<<<(NA + 63) / 64, 256, K3_SMEM_BYTES>>>(W_A, b_A, out);
}

// round 12
// speedup vs baseline: 1.6806x; 1.0102x over previous
#include <cuda_runtime.h>

#define NA 100000
#define NP 3200000
#define FA 75
#define FPR 14
#define HH 50
#define FO 50
#define XS 52
typedef unsigned long long ull;

__device__ float g_AA[NA * HH];
__device__ float g_X1[NA * XS];
__device__ float g_X2[NA * XS];
__device__ float g_PA[NA * HH];

__device__ __forceinline__ float relu_(float x) { return fmaxf(x, 0.0f); }
__device__ __forceinline__ void fma2_(ull& d, ull a, ull b) {
    asm("fma.rn.f32x2 %0, %1, %2, %0;" : "+l"(d) : "l"(a), "l"(b));
}
__device__ __forceinline__ ull dup_(float x) {
    ull r; asm("mov.b64 %0, {%1, %1};" : "=l"(r) : "f"(x)); return r;
}
__device__ __forceinline__ float2 unpk_(ull v) {
    float2 f; asm("mov.b64 {%0, %1}, %2;" : "=f"(f.x), "=f"(f.y) : "l"(v)); return f;
}

// ============ K1: atom precompute (proven) ============
__global__ __launch_bounds__(256) void atom_pre_kernel(
    const float* __restrict__ af, const float* __restrict__ W_AA,
    const float* __restrict__ b_AA, const float* __restrict__ W_AP)
{
    __shared__ __align__(16) float AsT[76 * 68];
    __shared__ __align__(16) float BsT[76 * 68];
    __shared__ float bsh[64];
    const int abase = blockIdx.x * 64;
    const int tid = threadIdx.x;

    for (int idx = tid; idx < 64 * 76; idx += 256) {
        int k = idx % 76, m = idx / 76;
        int a = abase + m;
        AsT[k * 68 + m] = (k < FA && a < NA) ? af[a * FA + k] : 0.0f;
    }
    for (int idx = tid; idx < 64 * HH; idx += 256) {
        int m = idx / HH, o = idx % HH;
        int a = abase + m;
        if (a < NA) g_PA[a * HH + o] = 0.0f;
    }
    for (int idx = tid; idx < 64 * 2; idx += 256) {
        int m = idx >> 1, o = 50 + (idx & 1);
        int a = abase + m;
        if (a < NA) { g_X1[(size_t)a * XS + o] = 0.0f; g_X2[(size_t)a * XS + o] = 0.0f; }
    }
    if (tid < 64) bsh[tid] = (tid < HH) ? b_AA[tid] : 0.0f;

    const int tm = tid >> 4, tn = tid & 15;
    const int m0 = tm * 4, n0 = tn * 4;

    for (int mat = 0; mat < 3; mat++) {
        __syncthreads();
        const float* W; int ws, wo;
        if (mat == 0) { W = W_AA; ws = FA;     wo = 0; }
        else          { W = W_AP; ws = 2 * FA; wo = (mat == 1) ? 0 : FA; }
        for (int idx = tid; idx < 64 * 76; idx += 256) {
            int k = idx % 76, o = idx / 76;
            BsT[k * 68 + o] = (k < FA && o < HH) ? W[o * ws + wo + k] : 0.0f;
        }
        __syncthreads();
        ull acc2[2][4];
#pragma unroll
        for (int rp = 0; rp < 2; rp++)
#pragma unroll
            for (int c = 0; c < 4; c++) acc2[rp][c] = 0ull;
#pragma unroll 5
        for (int k = 0; k < 75; k++) {
            ulonglong2 a2 = *(const ulonglong2*)&AsT[k * 68 + m0];
            float4 b4 = *(const float4*)&BsT[k * 68 + n0];
            ull av[2] = {a2.x, a2.y};
            ull bd[4] = {dup_(b4.x), dup_(b4.y), dup_(b4.z), dup_(b4.w)};
#pragma unroll
            for (int rp = 0; rp < 2; rp++)
#pragma unroll
                for (int c = 0; c < 4; c++) fma2_(acc2[rp][c], av[rp], bd[c]);
        }
        float* dst = (mat == 0) ? g_AA : ((mat == 1) ? g_X1 : g_X2);
        const int ds = (mat == 0) ? HH : XS;
#pragma unroll
        for (int rp = 0; rp < 2; rp++)
#pragma unroll
            for (int c = 0; c < 4; c++) {
                int o = n0 + c;
                if (o < HH) {
                    float2 f2 = unpk_(acc2[rp][c]);
                    int a0 = abase + m0 + 2 * rp;
                    if (mat == 0) { f2.x = relu_(f2.x + bsh[o]); f2.y = relu_(f2.y + bsh[o]); }
                    if (a0 < NA)     dst[(size_t)a0 * ds + o]       = f2.x;
                    if (a0 + 1 < NA) dst[(size_t)(a0 + 1) * ds + o] = f2.y;
                }
            }
    }
}

// ============ K2: persistent pair kernel, fused phases ============
// 64-pair tiles, 3 CTAs/SM, 4 barriers/tile.
// CT rows 0..49: PA (phase A) then PP (phase C1).  rows 50..99: S (phase A).
// WT row map: rows 0..49 <- W_P cols 50..99 (PP part); rows 50..99 <- cols 0..49 (S part).
#define NT (NP / 64)
#define GRID_P 444
#define PAIR_SMEM_BYTES (17336 * 4)

__global__ __launch_bounds__(256, 3) void pair_kernel(
    const float* __restrict__ pf, const int* __restrict__ split,
    const int* __restrict__ atp,
    const float* __restrict__ W_PA, const float* __restrict__ b_PA,
    const float* __restrict__ W_PP, const float* __restrict__ b_PP,
    const float* __restrict__ W_P,  const float* __restrict__ b_P,
    const float* __restrict__ b_AP, float* __restrict__ outP)
{
    extern __shared__ __align__(16) float sm[];
    float* CT   = sm;              // [100][68]
    float* WT   = CT + 6800;       // [100][68]  (row-remapped W_P^T)
    float* pfT  = WT + 6800;       // [16][68]
    float* WpaT = pfT + 1088;      // [16][68]
    float* WppT = WpaT + 1088;     // [16][68]
    float* sbAP = WppT + 1088;     // 52
    float* sbPP = sbAP + 52;
    float* sbPA = sbPP + 52;
    float* sbP  = sbPA + 52;
    int* sidx   = (int*)(sbP + 52);   // 128
    int* spsv   = sidx + 128;         // 68
    int* shead  = spsv + 68;          // 64
    int* snh    = shead + 64;         // 1

    const int tid = threadIdx.x;
    const int tm = tid >> 4, tn = tid & 15;
    const int m0 = tm * 4, n0 = tn * 4;

    // one-time weight staging (WT rows remapped: PP part first, S part second)
    for (int idx = tid; idx < 6400; idx += 256) {
        int r = idx % 100, o = idx / 100;
        int kk = (r < 50) ? (r + 50) : (r - 50);
        WT[r * 68 + o] = (o < FO) ? W_P[o * 2 * HH + kk] : 0.0f;
    }
    for (int idx = tid; idx < 1024; idx += 256) {
        int k = idx & 15, o = idx >> 4;
        bool v = (k < FPR && o < HH);
        WpaT[k * 68 + o] = v ? W_PA[o * FPR + k] : 0.0f;
        WppT[k * 68 + o] = v ? W_PP[o * FPR + k] : 0.0f;
    }
    if (tid < 52) {
        sbAP[tid] = (tid < HH) ? b_AP[tid] : 0.0f;
        sbPP[tid] = (tid < HH) ? b_PP[tid] : 0.0f;
        sbPA[tid] = (tid < HH) ? b_PA[tid] : 0.0f;
        sbP[tid]  = (tid < FO) ? b_P[tid]  : 0.0f;
    }
    // stage first tile inputs
    {
        int t0 = blockIdx.x;
        if (t0 < NT) {
            int p0 = t0 * 64;
            for (int idx = tid; idx < 1024; idx += 256) {
                int kk = idx & 15, p = idx >> 4;
                pfT[kk * 68 + p] = (kk < FPR) ? __ldcs(&pf[(size_t)(p0 + p) * FPR + kk]) : 0.0f;
            }
            if (tid < 128) sidx[tid] = atp[(size_t)p0 * 2 + tid];
            if (tid < 65)  spsv[tid] = (tid == 0) ? -1 : split[p0 + tid - 1];
            if (tid == 0)  *snh = 0;
        }
    }
    __syncthreads();

    for (int t = blockIdx.x; t < NT; t += GRID_P) {
        const int p0 = t * 64;

        // ======== Phase A: S gathers -> rows 50..99, head-detect, P1 -> rows 0..49 ========
        for (int idx = tid; idx < 64 * 13; idx += 256) {
            int p = idx / 13, c = idx % 13;
            int k0 = c * 4;
            int i = sidx[2 * p], j = sidx[2 * p + 1];
            float4 a = *(const float4*)(g_X1 + (size_t)i * XS + k0);
            float4 b = *(const float4*)(g_X2 + (size_t)j * XS + k0);
            float4 d = *(const float4*)(g_X1 + (size_t)j * XS + k0);
            float4 e = *(const float4*)(g_X2 + (size_t)i * XS + k0);
            float4 bi = *(const float4*)(sbAP + k0);
            CT[(50 + k0 + 0) * 68 + p] = relu_(a.x + b.x + bi.x) + relu_(d.x + e.x + bi.x);
            CT[(50 + k0 + 1) * 68 + p] = relu_(a.y + b.y + bi.y) + relu_(d.y + e.y + bi.y);
            if (c < 12) {
                CT[(50 + k0 + 2) * 68 + p] = relu_(a.z + b.z + bi.z) + relu_(d.z + e.z + bi.z);
                CT[(50 + k0 + 3) * 68 + p] = relu_(a.w + b.w + bi.w) + relu_(d.w + e.w + bi.w);
            }
        }
        if (tid < 64 && spsv[tid + 1] != spsv[tid]) shead[atomicAdd(snh, 1)] = tid;
        {   // P1: PA -> CT rows 0..49
            ull acc2[2][4];
#pragma unroll
            for (int rp = 0; rp < 2; rp++)
#pragma unroll
                for (int c = 0; c < 4; c++) acc2[rp][c] = 0ull;
#pragma unroll
            for (int k = 0; k < FPR; k++) {
                float4 b4 = *(const float4*)&WpaT[k * 68 + n0];
                ulonglong2 a2 = *(const ulonglong2*)&pfT[k * 68 + m0];
                ull av[2] = {a2.x, a2.y};
                ull bd[4] = {dup_(b4.x), dup_(b4.y), dup_(b4.z), dup_(b4.w)};
#pragma unroll
                for (int rp = 0; rp < 2; rp++)
#pragma unroll
                    for (int c = 0; c < 4; c++) fma2_(acc2[rp][c], av[rp], bd[c]);
            }
#pragma unroll
            for (int c = 0; c < 4; c++) {
                int o = n0 + c;
                if (o < HH) {
                    float b = sbPA[o];
#pragma unroll
                    for (int rp = 0; rp < 2; rp++) {
                        float2 f2 = unpk_(acc2[rp][c]);
                        *(float2*)&CT[o * 68 + m0 + 2 * rp] =
                            make_float2(relu_(f2.x + b), relu_(f2.y + b));
                    }
                }
            }
        }
        __syncthreads();

        // ======== Phase B: P2 (reads rows 0..49) + PP -> registers ========
        ull ppacc[2][4];
#pragma unroll
        for (int rp = 0; rp < 2; rp++)
#pragma unroll
            for (int c = 0; c < 4; c++) ppacc[rp][c] = 0ull;
        {
            int nh = *snh;
            for (int w = tid; w < nh * 64; w += 256) {
                int o = w & 63, hi = w >> 6;
                if (o < HH) {
                    int h = shead[hi];
                    int seg = spsv[h + 1];
                    float s = 0.0f;
                    int q = h;
                    while (q < 64 && spsv[q + 1] == seg) { s += CT[o * 68 + q]; q++; }
                    atomicAdd(&g_PA[(size_t)seg * HH + o], s);
                }
            }
        }
#pragma unroll
        for (int k = 0; k < FPR; k++) {
            float4 b4 = *(const float4*)&WppT[k * 68 + n0];
            ulonglong2 a2 = *(const ulonglong2*)&pfT[k * 68 + m0];
            ull av[2] = {a2.x, a2.y};
            ull bd[4] = {dup_(b4.x), dup_(b4.y), dup_(b4.z), dup_(b4.w)};
#pragma unroll
            for (int rp = 0; rp < 2; rp++)
#pragma unroll
                for (int c = 0; c < 4; c++) fma2_(ppacc[rp][c], av[rp], bd[c]);
        }
        __syncthreads();

        // ======== Phase C1: PP store -> rows 0..49 ========
#pragma unroll
        for (int c = 0; c < 4; c++) {
            int o = n0 + c;
            if (o < HH) {
                float b = sbPP[o];
#pragma unroll
                for (int rp = 0; rp < 2; rp++) {
                    float2 f2 = unpk_(ppacc[rp][c]);
                    *(float2*)&CT[o * 68 + m0 + 2 * rp] =
                        make_float2(relu_(f2.x + b), relu_(f2.y + b));
                }
            }
        }
        __syncthreads();

        // ======== Phase C2: P4 + stage next tile ========
        {
            // stage next tile inputs first (LDGs issue, latency hidden by P4 FMA)
            int tn2 = t + GRID_P;
            if (tn2 < NT) {
                int pn = tn2 * 64;
                for (int idx = tid; idx < 1024; idx += 256) {
                    int kk = idx & 15, p = idx >> 4;
                    pfT[kk * 68 + p] = (kk < FPR) ? __ldcs(&pf[(size_t)(pn + p) * FPR + kk]) : 0.0f;
                }
                if (tid < 128) sidx[tid] = atp[(size_t)pn * 2 + tid];
                if (tid < 65)  spsv[tid] = (tid == 0) ? -1 : split[pn + tid - 1];
                if (tid == 0)  *snh = 0;
            }
            ull acc2[2][4];
#pragma unroll
            for (int rp = 0; rp < 2; rp++)
#pragma unroll
                for (int c = 0; c < 4; c++) acc2[rp][c] = 0ull;
#pragma unroll 4
            for (int k = 0; k < 100; k++) {
                float4 b4 = *(const float4*)&WT[k * 68 + n0];
                ulonglong2 a2 = *(const ulonglong2*)&CT[k * 68 + m0];
                ull av[2] = {a2.x, a2.y};
                ull bd[4] = {dup_(b4.x), dup_(b4.y), dup_(b4.z), dup_(b4.w)};
#pragma unroll
                for (int rp = 0; rp < 2; rp++)
#pragma unroll
                    for (int c = 0; c < 4; c++) fma2_(acc2[rp][c], av[rp], bd[c]);
            }
            if (n0 < FO) {
                float accf[4][4];
#pragma unroll
                for (int rp = 0; rp < 2; rp++)
#pragma unroll
                    for (int c = 0; c < 4; c++) {
                        float2 f2 = unpk_(acc2[rp][c]);
                        accf[2 * rp][c] = f2.x;
                        accf[2 * rp + 1][c] = f2.y;
                    }
                float bb[4];
#pragma unroll
                for (int c = 0; c < 4; c++) bb[c] = sbP[n0 + c];
                bool full = (n0 + 3 < FO);
#pragma unroll
                for (int r = 0; r < 4; r++) {
                    size_t p = (size_t)(p0 + m0 + r);
                    float* dst = &outP[p * FO + n0];
                    __stcs((float2*)dst,
                           make_float2(relu_(accf[r][0] + bb[0]), relu_(accf[r][1] + bb[1])));
                    if (full)
                        __stcs((float2*)(dst + 2),
                               make_float2(relu_(accf[r][2] + bb[2]), relu_(accf[r][3] + bb[3])));
                }
            }
        }
        __syncthreads();
    }
}

// ============ K3: A-output (proven) ============
#define K3_SMEM_BYTES ((100*68*2 + 64) * 4)
__global__ __launch_bounds__(256) void atom_out_kernel(
    const float* __restrict__ W_A, const float* __restrict__ b_A,
    float* __restrict__ outA)
{
    extern __shared__ __align__(16) float sm3[];
    float* CcT = sm3;
    float* BsT = CcT + 100 * 68;
    float* bsh = BsT + 100 * 68;
    const int abase = blockIdx.x * 64;
    const int tid = threadIdx.x;

    for (int idx = tid; idx < 64 * 100; idx += 256) {
        int k = idx % 100, m = idx / 100;
        int a = abase + m;
        float v = 0.0f;
        if (a < NA) v = (k < HH) ? g_AA[a * HH + k] : g_PA[a * HH + (k - HH)];
        CcT[k * 68 + m] = v;
    }
    for (int idx = tid; idx < 64 * 100; idx += 256) {
        int k = idx % 100, o = idx / 100;
        BsT[k * 68 + o] = (o < FO) ? W_A[o * 2 * HH + k] : 0.0f;
    }
    if (tid < 64) bsh[tid] = (tid < FO) ? b_A[tid] : 0.0f;
    __syncthreads();

    const int tm = tid >> 4, tn = tid & 15;
    const int m0 = tm * 4, n0 = tn * 4;
    ull acc2[2][4];
#pragma unroll
    for (int rp = 0; rp < 2; rp++)
#pragma unroll
        for (int c = 0; c < 4; c++) acc2[rp][c] = 0ull;
#pragma unroll 4
    for (int k = 0; k < 100; k++) {
        ulonglong2 a2 = *(const ulonglong2*)&CcT[k * 68 + m0];
        float4 b4 = *(const float4*)&BsT[k * 68 + n0];
        ull av[2] = {a2.x, a2.y};
        ull bd[4] = {dup_(b4.x), dup_(b4.y), dup_(b4.z), dup_(b4.w)};
#pragma unroll
        for (int rp = 0; rp < 2; rp++)
#pragma unroll
            for (int c = 0; c < 4; c++) fma2_(acc2[rp][c], av[rp], bd[c]);
    }
#pragma unroll
    for (int rp = 0; rp < 2; rp++)
#pragma unroll
        for (int c = 0; c < 4; c++) {
            int o = n0 + c;
            if (o < FO) {
                float2 f2 = unpk_(acc2[rp][c]);
                int a0 = abase + m0 + 2 * rp;
                if (a0 < NA)     outA[(size_t)a0 * FO + o]       = relu_(f2.x + bsh[o]);
                if (a0 + 1 < NA) outA[(size_t)(a0 + 1) * FO + o] = relu_(f2.y + bsh[o]);
            }
        }
}

extern "C" void kernel_launch(void* const* d_in, const int* in_sizes, int n_in,
                              void* d_out, int out_size)
{
    const float* af    = (const float*)d_in[0];
    const float* pf    = (const float*)d_in[1];
    const int*   split = (const int*)  d_in[2];
    const int*   atp   = (const int*)  d_in[3];
    const float* W_AA  = (const float*)d_in[4];
    const float* b_AA  = (const float*)d_in[5];
    const float* W_PA  = (const float*)d_in[6];
    const float* b_PA  = (const float*)d_in[7];
    const float* W_A   = (const float*)d_in[8];
    const float* b_A   = (const float*)d_in[9];
    const float* W_AP  = (const float*)d_in[10];
    const float* b_AP  = (const float*)d_in[11];
    const float* W_PP  = (const float*)d_in[12];
    const float* b_PP  = (const float*)d_in[13];
    const float* W_P   = (const float*)d_in[14];
    const float* b_P   = (const float*)d_in[15];
    float* out = (float*)d_out;

    cudaFuncSetAttribute(pair_kernel, cudaFuncAttributeMaxDynamicSharedMemorySize, PAIR_SMEM_BYTES);
    cudaFuncSetAttribute(atom_out_kernel, cudaFuncAttributeMaxDynamicSharedMemorySize, K3_SMEM_BYTES);

    atom_pre_kernel<<<(NA + 63) / 64, 256>>>(af, W_AA, b_AA, W_AP);

    pair_kernel<<<GRID_P, 256, PAIR_SMEM_BYTES>>>(
        pf, split, atp, W_PA, b_PA, W_PP, b_PP, W_P, b_P, b_AP,
        out + (size_t)NA * FO);

    atom_out_kernel<<<(NA + 63) / 64, 256, K3_SMEM_BYTES>>>(W_A, b_A, out);
}

// round 13
// speedup vs baseline: 1.7682x; 1.0521x over previous
#include <cuda_runtime.h>

#define NA 100000
#define NP 3200000
#define FA 75
#define FPR 14
#define HH 50
#define FO 50
#define XS 52
typedef unsigned long long ull;

__device__ float g_AA[NA * HH];
__device__ float g_X1[NA * XS];
__device__ float g_X2[NA * XS];
__device__ float g_PA[NA * HH];

__device__ __forceinline__ float relu_(float x) { return fmaxf(x, 0.0f); }
__device__ __forceinline__ void fma2_(ull& d, ull a, ull b) {
    asm("fma.rn.f32x2 %0, %1, %2, %0;" : "+l"(d) : "l"(a), "l"(b));
}
__device__ __forceinline__ ull dup_(float x) {
    ull r; asm("mov.b64 %0, {%1, %1};" : "=l"(r) : "f"(x)); return r;
}
__device__ __forceinline__ float2 unpk_(ull v) {
    float2 f; asm("mov.b64 {%0, %1}, %2;" : "=f"(f.x), "=f"(f.y) : "l"(v)); return f;
}

// ============ K1: atom precompute (proven) ============
__global__ __launch_bounds__(256) void atom_pre_kernel(
    const float* __restrict__ af, const float* __restrict__ W_AA,
    const float* __restrict__ b_AA, const float* __restrict__ W_AP)
{
    __shared__ __align__(16) float AsT[76 * 68];
    __shared__ __align__(16) float BsT[76 * 68];
    __shared__ float bsh[64];
    const int abase = blockIdx.x * 64;
    const int tid = threadIdx.x;

    for (int idx = tid; idx < 64 * 76; idx += 256) {
        int k = idx % 76, m = idx / 76;
        int a = abase + m;
        AsT[k * 68 + m] = (k < FA && a < NA) ? af[a * FA + k] : 0.0f;
    }
    for (int idx = tid; idx < 64 * HH; idx += 256) {
        int m = idx / HH, o = idx % HH;
        int a = abase + m;
        if (a < NA) g_PA[a * HH + o] = 0.0f;
    }
    for (int idx = tid; idx < 64 * 2; idx += 256) {
        int m = idx >> 1, o = 50 + (idx & 1);
        int a = abase + m;
        if (a < NA) { g_X1[(size_t)a * XS + o] = 0.0f; g_X2[(size_t)a * XS + o] = 0.0f; }
    }
    if (tid < 64) bsh[tid] = (tid < HH) ? b_AA[tid] : 0.0f;

    const int tm = tid >> 4, tn = tid & 15;
    const int m0 = tm * 4, n0 = tn * 4;

    for (int mat = 0; mat < 3; mat++) {
        __syncthreads();
        const float* W; int ws, wo;
        if (mat == 0) { W = W_AA; ws = FA;     wo = 0; }
        else          { W = W_AP; ws = 2 * FA; wo = (mat == 1) ? 0 : FA; }
        for (int idx = tid; idx < 64 * 76; idx += 256) {
            int k = idx % 76, o = idx / 76;
            BsT[k * 68 + o] = (k < FA && o < HH) ? W[o * ws + wo + k] : 0.0f;
        }
        __syncthreads();
        ull acc2[2][4];
#pragma unroll
        for (int rp = 0; rp < 2; rp++)
#pragma unroll
            for (int c = 0; c < 4; c++) acc2[rp][c] = 0ull;
#pragma unroll 5
        for (int k = 0; k < 75; k++) {
            ulonglong2 a2 = *(const ulonglong2*)&AsT[k * 68 + m0];
            float4 b4 = *(const float4*)&BsT[k * 68 + n0];
            ull av[2] = {a2.x, a2.y};
            ull bd[4] = {dup_(b4.x), dup_(b4.y), dup_(b4.z), dup_(b4.w)};
#pragma unroll
            for (int rp = 0; rp < 2; rp++)
#pragma unroll
                for (int c = 0; c < 4; c++) fma2_(acc2[rp][c], av[rp], bd[c]);
        }
        float* dst = (mat == 0) ? g_AA : ((mat == 1) ? g_X1 : g_X2);
        const int ds = (mat == 0) ? HH : XS;
#pragma unroll
        for (int rp = 0; rp < 2; rp++)
#pragma unroll
            for (int c = 0; c < 4; c++) {
                int o = n0 + c;
                if (o < HH) {
                    float2 f2 = unpk_(acc2[rp][c]);
                    int a0 = abase + m0 + 2 * rp;
                    if (mat == 0) { f2.x = relu_(f2.x + bsh[o]); f2.y = relu_(f2.y + bsh[o]); }
                    if (a0 < NA)     dst[(size_t)a0 * ds + o]       = f2.x;
                    if (a0 + 1 < NA) dst[(size_t)(a0 + 1) * ds + o] = f2.y;
                }
            }
    }
}

// ============ K2: persistent pair kernel, fused phases, ballot segsum ============
// 64-pair tiles, 3 CTAs/SM, 4 barriers/tile.
// CT rows 0..49: PA (phase A) then PP (phase C1).  rows 50..99: S (phase A).
// WT row map: rows 0..49 <- W_P cols 50..99 (PP part); rows 50..99 <- cols 0..49 (S part).
#define NT (NP / 64)
#define GRID_P 444
#define PAIR_SMEM_BYTES (17336 * 4)

__global__ __launch_bounds__(256, 3) void pair_kernel(
    const float* __restrict__ pf, const int* __restrict__ split,
    const int* __restrict__ atp,
    const float* __restrict__ W_PA, const float* __restrict__ b_PA,
    const float* __restrict__ W_PP, const float* __restrict__ b_PP,
    const float* __restrict__ W_P,  const float* __restrict__ b_P,
    const float* __restrict__ b_AP, float* __restrict__ outP)
{
    extern __shared__ __align__(16) float sm[];
    float* CT   = sm;              // [100][68]
    float* WT   = CT + 6800;       // [100][68]  (row-remapped W_P^T)
    float* pfT  = WT + 6800;       // [16][68]
    float* WpaT = pfT + 1088;      // [16][68]
    float* WppT = WpaT + 1088;     // [16][68]
    float* sbAP = WppT + 1088;     // 52
    float* sbPP = sbAP + 52;
    float* sbPA = sbPP + 52;
    float* sbP  = sbPA + 52;
    int* sidx   = (int*)(sbP + 52);   // 128
    int* spsv   = sidx + 128;         // 68
    int* sbal   = spsv + 68;          // 2 (head ballot, 64 bits)

    const int tid = threadIdx.x;
    const int tm = tid >> 4, tn = tid & 15;
    const int m0 = tm * 4, n0 = tn * 4;

    // one-time weight staging (WT rows remapped: PP part first, S part second)
    for (int idx = tid; idx < 6400; idx += 256) {
        int r = idx % 100, o = idx / 100;
        int kk = (r < 50) ? (r + 50) : (r - 50);
        WT[r * 68 + o] = (o < FO) ? W_P[o * 2 * HH + kk] : 0.0f;
    }
    for (int idx = tid; idx < 1024; idx += 256) {
        int k = idx & 15, o = idx >> 4;
        bool v = (k < FPR && o < HH);
        WpaT[k * 68 + o] = v ? W_PA[o * FPR + k] : 0.0f;
        WppT[k * 68 + o] = v ? W_PP[o * FPR + k] : 0.0f;
    }
    if (tid < 52) {
        sbAP[tid] = (tid < HH) ? b_AP[tid] : 0.0f;
        sbPP[tid] = (tid < HH) ? b_PP[tid] : 0.0f;
        sbPA[tid] = (tid < HH) ? b_PA[tid] : 0.0f;
        sbP[tid]  = (tid < FO) ? b_P[tid]  : 0.0f;
    }
    // stage first tile inputs
    {
        int t0 = blockIdx.x;
        if (t0 < NT) {
            int p0 = t0 * 64;
            for (int idx = tid; idx < 1024; idx += 256) {
                int kk = idx & 15, p = idx >> 4;
                pfT[kk * 68 + p] = (kk < FPR) ? __ldcs(&pf[(size_t)(p0 + p) * FPR + kk]) : 0.0f;
            }
            if (tid < 128) sidx[tid] = atp[(size_t)p0 * 2 + tid];
            if (tid < 65)  spsv[tid] = (tid == 0) ? -1 : split[p0 + tid - 1];
        }
    }
    __syncthreads();

    for (int t = blockIdx.x; t < NT; t += GRID_P) {
        const int p0 = t * 64;

        // ======== Phase A: S gathers -> rows 50..99, ballot head-detect, P1 -> rows 0..49 ========
        if (tid < 64) {
            bool ish = (spsv[tid + 1] != spsv[tid]);   // forced head at tid=0 (spsv[0]=-1)
            unsigned bm = __ballot_sync(0xffffffffu, ish);
            if ((tid & 31) == 0) sbal[tid >> 5] = (int)bm;
        }
        for (int idx = tid; idx < 64 * 13; idx += 256) {
            int p = idx / 13, c = idx % 13;
            int k0 = c * 4;
            int i = sidx[2 * p], j = sidx[2 * p + 1];
            float4 a = *(const float4*)(g_X1 + (size_t)i * XS + k0);
            float4 b = *(const float4*)(g_X2 + (size_t)j * XS + k0);
            float4 d = *(const float4*)(g_X1 + (size_t)j * XS + k0);
            float4 e = *(const float4*)(g_X2 + (size_t)i * XS + k0);
            float4 bi = *(const float4*)(sbAP + k0);
            CT[(50 + k0 + 0) * 68 + p] = relu_(a.x + b.x + bi.x) + relu_(d.x + e.x + bi.x);
            CT[(50 + k0 + 1) * 68 + p] = relu_(a.y + b.y + bi.y) + relu_(d.y + e.y + bi.y);
            if (c < 12) {
                CT[(50 + k0 + 2) * 68 + p] = relu_(a.z + b.z + bi.z) + relu_(d.z + e.z + bi.z);
                CT[(50 + k0 + 3) * 68 + p] = relu_(a.w + b.w + bi.w) + relu_(d.w + e.w + bi.w);
            }
        }
        {   // P1: PA -> CT rows 0..49
            ull acc2[2][4];
#pragma unroll
            for (int rp = 0; rp < 2; rp++)
#pragma unroll
                for (int c = 0; c < 4; c++) acc2[rp][c] = 0ull;
#pragma unroll
            for (int k = 0; k < FPR; k++) {
                float4 b4 = *(const float4*)&WpaT[k * 68 + n0];
                ulonglong2 a2 = *(const ulonglong2*)&pfT[k * 68 + m0];
                ull av[2] = {a2.x, a2.y};
                ull bd[4] = {dup_(b4.x), dup_(b4.y), dup_(b4.z), dup_(b4.w)};
#pragma unroll
                for (int rp = 0; rp < 2; rp++)
#pragma unroll
                    for (int c = 0; c < 4; c++) fma2_(acc2[rp][c], av[rp], bd[c]);
            }
#pragma unroll
            for (int c = 0; c < 4; c++) {
                int o = n0 + c;
                if (o < HH) {
                    float b = sbPA[o];
#pragma unroll
                    for (int rp = 0; rp < 2; rp++) {
                        float2 f2 = unpk_(acc2[rp][c]);
                        *(float2*)&CT[o * 68 + m0 + 2 * rp] =
                            make_float2(relu_(f2.x + b), relu_(f2.y + b));
                    }
                }
            }
        }
        __syncthreads();

        // ======== Phase B: segsum (ballot-derived bounds, vectorized) + PP -> regs ========
        ull ppacc[2][4];
#pragma unroll
        for (int rp = 0; rp < 2; rp++)
#pragma unroll
            for (int c = 0; c < 4; c++) ppacc[rp][c] = 0ull;
        {
            ull mask = (ull)(unsigned)sbal[0] | ((ull)(unsigned)sbal[1] << 32);
            int nh = __popcll(mask);
            for (int w = tid; w < nh * 64; w += 256) {
                int o = w & 63, hi = w >> 6;
                if (o < HH) {
                    // h = position of hi-th set bit (hi small: avg ~2)
                    ull mm = mask;
                    for (int it = 0; it < hi; it++) mm &= mm - 1;
                    int h = __ffsll((long long)mm) - 1;
                    int e;
                    if (h >= 63) e = 64;
                    else {
                        ull rest = mask >> (h + 1);
                        e = rest ? (h + 1 + __ffsll((long long)rest) - 1) : 64;
                    }
                    int seg = spsv[h + 1];
                    const float* cr = &CT[o * 68];
                    float s = 0.0f;
                    int q = h;
                    int e4 = h + ((e - h) & ~3);
                    for (; q < e4; q += 4)
                        s += (cr[q] + cr[q + 1]) + (cr[q + 2] + cr[q + 3]);
                    for (; q < e; q++) s += cr[q];
                    atomicAdd(&g_PA[(size_t)seg * HH + o], s);
                }
            }
        }
#pragma unroll
        for (int k = 0; k < FPR; k++) {
            float4 b4 = *(const float4*)&WppT[k * 68 + n0];
            ulonglong2 a2 = *(const ulonglong2*)&pfT[k * 68 + m0];
            ull av[2] = {a2.x, a2.y};
            ull bd[4] = {dup_(b4.x), dup_(b4.y), dup_(b4.z), dup_(b4.w)};
#pragma unroll
            for (int rp = 0; rp < 2; rp++)
#pragma unroll
                for (int c = 0; c < 4; c++) fma2_(ppacc[rp][c], av[rp], bd[c]);
        }
        __syncthreads();

        // ======== Phase C1: PP store -> rows 0..49 ========
#pragma unroll
        for (int c = 0; c < 4; c++) {
            int o = n0 + c;
            if (o < HH) {
                float b = sbPP[o];
#pragma unroll
                for (int rp = 0; rp < 2; rp++) {
                    float2 f2 = unpk_(ppacc[rp][c]);
                    *(float2*)&CT[o * 68 + m0 + 2 * rp] =
                        make_float2(relu_(f2.x + b), relu_(f2.y + b));
                }
            }
        }
        __syncthreads();

        // ======== Phase C2: P4 + stage next tile ========
        {
            int tn2 = t + GRID_P;
            if (tn2 < NT) {
                int pn = tn2 * 64;
                for (int idx = tid; idx < 1024; idx += 256) {
                    int kk = idx & 15, p = idx >> 4;
                    pfT[kk * 68 + p] = (kk < FPR) ? __ldcs(&pf[(size_t)(pn + p) * FPR + kk]) : 0.0f;
                }
                if (tid < 128) sidx[tid] = atp[(size_t)pn * 2 + tid];
                if (tid < 65)  spsv[tid] = (tid == 0) ? -1 : split[pn + tid - 1];
            }
            ull acc2[2][4];
#pragma unroll
            for (int rp = 0; rp < 2; rp++)
#pragma unroll
                for (int c = 0; c < 4; c++) acc2[rp][c] = 0ull;
#pragma unroll 4
            for (int k = 0; k < 100; k++) {
                float4 b4 = *(const float4*)&WT[k * 68 + n0];
                ulonglong2 a2 = *(const ulonglong2*)&CT[k * 68 + m0];
                ull av[2] = {a2.x, a2.y};
                ull bd[4] = {dup_(b4.x), dup_(b4.y), dup_(b4.z), dup_(b4.w)};
#pragma unroll
                for (int rp = 0; rp < 2; rp++)
#pragma unroll
                    for (int c = 0; c < 4; c++) fma2_(acc2[rp][c], av[rp], bd[c]);
            }
            if (n0 < FO) {
                float accf[4][4];
#pragma unroll
                for (int rp = 0; rp < 2; rp++)
#pragma unroll
                    for (int c = 0; c < 4; c++) {
                        float2 f2 = unpk_(acc2[rp][c]);
                        accf[2 * rp][c] = f2.x;
                        accf[2 * rp + 1][c] = f2.y;
                    }
                float bb[4];
#pragma unroll
                for (int c = 0; c < 4; c++) bb[c] = sbP[n0 + c];
                bool full = (n0 + 3 < FO);
#pragma unroll
                for (int r = 0; r < 4; r++) {
                    size_t p = (size_t)(p0 + m0 + r);
                    float* dst = &outP[p * FO + n0];
                    __stcs((float2*)dst,
                           make_float2(relu_(accf[r][0] + bb[0]), relu_(accf[r][1] + bb[1])));
                    if (full)
                        __stcs((float2*)(dst + 2),
                               make_float2(relu_(accf[r][2] + bb[2]), relu_(accf[r][3] + bb[3])));
                }
            }
        }
        __syncthreads();
    }
}

// ============ K3: A-output (proven) ============
#define K3_SMEM_BYTES ((100*68*2 + 64) * 4)
__global__ __launch_bounds__(256) void atom_out_kernel(
    const float* __restrict__ W_A, const float* __restrict__ b_A,
    float* __restrict__ outA)
{
    extern __shared__ __align__(16) float sm3[];
    float* CcT = sm3;
    float* BsT = CcT + 100 * 68;
    float* bsh = BsT + 100 * 68;
    const int abase = blockIdx.x * 64;
    const int tid = threadIdx.x;

    for (int idx = tid; idx < 64 * 100; idx += 256) {
        int k = idx % 100, m = idx / 100;
        int a = abase + m;
        float v = 0.0f;
        if (a < NA) v = (k < HH) ? g_AA[a * HH + k] : g_PA[a * HH + (k - HH)];
        CcT[k * 68 + m] = v;
    }
    for (int idx = tid; idx < 64 * 100; idx += 256) {
        int k = idx % 100, o = idx / 100;
        BsT[k * 68 + o] = (o < FO) ? W_A[o * 2 * HH + k] : 0.0f;
    }
    if (tid < 64) bsh[tid] = (tid < FO) ? b_A[tid] : 0.0f;
    __syncthreads();

    const int tm = tid >> 4, tn = tid & 15;
    const int m0 = tm * 4, n0 = tn * 4;
    ull acc2[2][4];
#pragma unroll
    for (int rp = 0; rp < 2; rp++)
#pragma unroll
        for (int c = 0; c < 4; c++) acc2[rp][c] = 0ull;
#pragma unroll 4
    for (int k = 0; k < 100; k++) {
        ulonglong2 a2 = *(const ulonglong2*)&CcT[k * 68 + m0];
        float4 b4 = *(const float4*)&BsT[k * 68 + n0];
        ull av[2] = {a2.x, a2.y};
        ull bd[4] = {dup_(b4.x), dup_(b4.y), dup_(b4.z), dup_(b4.w)};
#pragma unroll
        for (int rp = 0; rp < 2; rp++)
#pragma unroll
            for (int c = 0; c < 4; c++) fma2_(acc2[rp][c], av[rp], bd[c]);
    }
#pragma unroll
    for (int rp = 0; rp < 2; rp++)
#pragma unroll
        for (int c = 0; c < 4; c++) {
            int o = n0 + c;
            if (o < FO) {
                float2 f2 = unpk_(acc2[rp][c]);
                int a0 = abase + m0 + 2 * rp;
                if (a0 < NA)     outA[(size_t)a0 * FO + o]       = relu_(f2.x + bsh[o]);
                if (a0 + 1 < NA) outA[(size_t)(a0 + 1) * FO + o] = relu_(f2.y + bsh[o]);
            }
        }
}

extern "C" void kernel_launch(void* const* d_in, const int* in_sizes, int n_in,
                              void* d_out, int out_size)
{
    const float* af    = (const float*)d_in[0];
    const float* pf    = (const float*)d_in[1];
    const int*   split = (const int*)  d_in[2];
    const int*   atp   = (const int*)  d_in[3];
    const float* W_AA  = (const float*)d_in[4];
    const float* b_AA  = (const float*)d_in[5];
    const float* W_PA  = (const float*)d_in[6];
    const float* b_PA  = (const float*)d_in[7];
    const float* W_A   = (const float*)d_in[8];
    const float* b_A   = (const float*)d_in[9];
    const float* W_AP  = (const float*)d_in[10];
    const float* b_AP  = (const float*)d_in[11];
    const float* W_PP  = (const float*)d_in[12];
    const float* b_PP  = (const float*)d_in[13];
    const float* W_P   = (const float*)d_in[14];
    const float* b_P   = (const float*)d_in[15];
    float* out = (float*)d_out;

    cudaFuncSetAttribute(pair_kernel, cudaFuncAttributeMaxDynamicSharedMemorySize, PAIR_SMEM_BYTES);
    cudaFuncSetAttribute(atom_out_kernel, cudaFuncAttributeMaxDynamicSharedMemorySize, K3_SMEM_BYTES);

    atom_pre_kernel<<<(NA + 63) / 64, 256>>>(af, W_AA, b_AA, W_AP);

    pair_kernel<<<GRID_P, 256, PAIR_SMEM_BYTES>>>(
        pf, split, atp, W_PA, b_PA, W_PP, b_PP, W_P, b_P, b_AP,
        out + (size_t)NA * FO);

    atom_out_kernel<<<(NA + 63) / 64, 256, K3_SMEM_BYTES>>>(W_A, b_A, out);
}